// round 1
// baseline (speedup 1.0000x reference)
#include <cuda_runtime.h>

// ---------------------------------------------------------------------------
// Problem constants (fixed shapes from the reference):
//   x1     [4, 4096, 1024]  fp32
//   W_qkv  [3072, 1024]     fp32   (row-major, K-contiguous)
//   b_qkv  [3072]           fp32
//   out    [4, 4096, 1024]  fp32
// Pipeline:
//   1) QKV = x1 @ W^T + b      (NT gemm, epilogue scatters into Q/K/V)
//   2) S   = (Q @ K^T) / 32    (NT gemm per batch)
//   3) P   = softmax_rows(S)
//   4) out = P @ V             (NN gemm per batch)
// ---------------------------------------------------------------------------

#define BATCH 4
#define SEQ   4096
#define DIM   1024
#define QKVN  3072

// Scratch: __device__ globals (no allocations allowed in kernel_launch).
__device__ float g_Q[(long)BATCH * SEQ * DIM];   //  64 MB
__device__ float g_K[(long)BATCH * SEQ * DIM];   //  64 MB
__device__ float g_V[(long)BATCH * SEQ * DIM];   //  64 MB
__device__ float g_S[(long)BATCH * SEQ * SEQ];   // 256 MB

// ---------------------------------------------------------------------------
// Shared 128x128x16 SGEMM core. 256 threads, each computes 8x8.
// A is [M,K] row-major. If TRANSB: B is [N,K] row-major (C = A * B^T).
// Else: B is [K,N] row-major (C = A * B).
// All of bm/bn/K assumed tile-aligned (true for every shape here).
// ---------------------------------------------------------------------------
template <bool TRANSB>
__device__ __forceinline__ void gemm_tile(const float* __restrict__ A, int lda,
                                          const float* __restrict__ B, int ldb,
                                          int K, int bm, int bn,
                                          float acc[8][8]) {
    __shared__ float As[16][128];   // A tile transposed: As[k][m]
    __shared__ float Bs[16][128];   // Bs[k][n]

    const int tid = threadIdx.x;
    const int ty = tid >> 4;        // 0..15
    const int tx = tid & 15;        // 0..15

#pragma unroll
    for (int i = 0; i < 8; i++)
#pragma unroll
        for (int j = 0; j < 8; j++) acc[i][j] = 0.0f;

    for (int k0 = 0; k0 < K; k0 += 16) {
        // ---- load A tile (transpose into As[k][m]) ----
        {
            const int r0 = tid >> 2;          // 0..63
            const int c4 = (tid & 3) * 4;     // 0,4,8,12
#pragma unroll
            for (int r = 0; r < 2; r++) {
                const int row = r0 + r * 64;
                float4 v = *(const float4*)(A + (long)(bm + row) * lda + k0 + c4);
                As[c4 + 0][row] = v.x;
                As[c4 + 1][row] = v.y;
                As[c4 + 2][row] = v.z;
                As[c4 + 3][row] = v.w;
            }
        }
        // ---- load B tile ----
        if (TRANSB) {
            const int r0 = tid >> 2;
            const int c4 = (tid & 3) * 4;
#pragma unroll
            for (int r = 0; r < 2; r++) {
                const int col = r0 + r * 64;
                float4 v = *(const float4*)(B + (long)(bn + col) * ldb + k0 + c4);
                Bs[c4 + 0][col] = v.x;
                Bs[c4 + 1][col] = v.y;
                Bs[c4 + 2][col] = v.z;
                Bs[c4 + 3][col] = v.w;
            }
        } else {
            const int kr = tid >> 5;          // 0..7
            const int c4 = (tid & 31) * 4;    // 0..124
#pragma unroll
            for (int r = 0; r < 2; r++) {
                const int krow = kr + r * 8;
                float4 v = *(const float4*)(B + (long)(k0 + krow) * ldb + bn + c4);
                *(float4*)&Bs[krow][c4] = v;
            }
        }
        __syncthreads();

#pragma unroll
        for (int kk = 0; kk < 16; kk++) {
            float a[8], b[8];
            *(float4*)&a[0] = *(const float4*)&As[kk][ty * 8];
            *(float4*)&a[4] = *(const float4*)&As[kk][ty * 8 + 4];
            *(float4*)&b[0] = *(const float4*)&Bs[kk][tx * 8];
            *(float4*)&b[4] = *(const float4*)&Bs[kk][tx * 8 + 4];
#pragma unroll
            for (int i = 0; i < 8; i++)
#pragma unroll
                for (int j = 0; j < 8; j++)
                    acc[i][j] = fmaf(a[i], b[j], acc[i][j]);
        }
        __syncthreads();
    }
}

// ---------------------------------------------------------------------------
// Kernel 1: QKV projection.  C[16384,3072] = X @ W^T + bias, scattered to Q/K/V.
// Each 128-wide column block lies entirely inside one of Q/K/V (1024 % 128 == 0).
// ---------------------------------------------------------------------------
__global__ void __launch_bounds__(256) qkv_gemm(const float* __restrict__ X,
                                                const float* __restrict__ W,
                                                const float* __restrict__ bias) {
    const int bm = blockIdx.y * 128;
    const int bn = blockIdx.x * 128;
    float acc[8][8];
    gemm_tile<true>(X, DIM, W, DIM, DIM, bm, bn, acc);

    const int ty = threadIdx.x >> 4;
    const int tx = threadIdx.x & 15;
    const int sel = bn >> 10;                  // 0:Q 1:K 2:V
    float* dst = (sel == 0) ? g_Q : (sel == 1) ? g_K : g_V;
    const int ncol = bn & 1023;

#pragma unroll
    for (int i = 0; i < 8; i++) {
        const int m = bm + ty * 8 + i;
        const long rowoff = (long)m * DIM;     // (b*SEQ+s)*DIM == m*DIM
#pragma unroll
        for (int j = 0; j < 8; j += 4) {
            const int gn = bn + tx * 8 + j;
            float4 v;
            v.x = acc[i][j + 0] + bias[gn + 0];
            v.y = acc[i][j + 1] + bias[gn + 1];
            v.z = acc[i][j + 2] + bias[gn + 2];
            v.w = acc[i][j + 3] + bias[gn + 3];
            *(float4*)(dst + rowoff + ncol + tx * 8 + j) = v;
        }
    }
}

// ---------------------------------------------------------------------------
// Kernel 2: scores.  S_b = (Q_b @ K_b^T) * (1/32)
// ---------------------------------------------------------------------------
__global__ void __launch_bounds__(256) scores_gemm() {
    const int z = blockIdx.z;
    const int bm = blockIdx.y * 128;
    const int bn = blockIdx.x * 128;
    const float* Qp = g_Q + (long)z * SEQ * DIM;
    const float* Kp = g_K + (long)z * SEQ * DIM;
    float* Sp = g_S + (long)z * SEQ * SEQ;

    float acc[8][8];
    gemm_tile<true>(Qp, DIM, Kp, DIM, DIM, bm, bn, acc);

    const float scale = 0.03125f;  // 1024^-0.5
    const int ty = threadIdx.x >> 4;
    const int tx = threadIdx.x & 15;
#pragma unroll
    for (int i = 0; i < 8; i++) {
        const long rowoff = (long)(bm + ty * 8 + i) * SEQ;
#pragma unroll
        for (int j = 0; j < 8; j += 4) {
            float4 v;
            v.x = acc[i][j + 0] * scale;
            v.y = acc[i][j + 1] * scale;
            v.z = acc[i][j + 2] * scale;
            v.w = acc[i][j + 3] * scale;
            *(float4*)(Sp + rowoff + bn + tx * 8 + j) = v;
        }
    }
}

// ---------------------------------------------------------------------------
// Kernel 3: row softmax over 4096 columns. One CTA (256 threads) per row.
// Row stays resident in registers (16 floats/thread).
// ---------------------------------------------------------------------------
__global__ void __launch_bounds__(256) softmax_kernel() {
    const long row = blockIdx.x;
    float* p = g_S + row * (long)SEQ;
    const int tid = threadIdx.x;
    const int warp = tid >> 5, lane = tid & 31;
    __shared__ float red[8];

    float4 v[4];
    float m = -3.402823466e38f;
#pragma unroll
    for (int i = 0; i < 4; i++) {
        v[i] = ((const float4*)p)[tid + i * 256];
        m = fmaxf(m, fmaxf(fmaxf(v[i].x, v[i].y), fmaxf(v[i].z, v[i].w)));
    }
#pragma unroll
    for (int o = 16; o > 0; o >>= 1) m = fmaxf(m, __shfl_xor_sync(0xffffffffu, m, o));
    if (lane == 0) red[warp] = m;
    __syncthreads();
    m = red[0];
#pragma unroll
    for (int w = 1; w < 8; w++) m = fmaxf(m, red[w]);
    __syncthreads();

    float sum = 0.0f;
#pragma unroll
    for (int i = 0; i < 4; i++) {
        v[i].x = __expf(v[i].x - m);
        v[i].y = __expf(v[i].y - m);
        v[i].z = __expf(v[i].z - m);
        v[i].w = __expf(v[i].w - m);
        sum += v[i].x + v[i].y + v[i].z + v[i].w;
    }
#pragma unroll
    for (int o = 16; o > 0; o >>= 1) sum += __shfl_xor_sync(0xffffffffu, sum, o);
    if (lane == 0) red[warp] = sum;
    __syncthreads();
    sum = red[0];
#pragma unroll
    for (int w = 1; w < 8; w++) sum += red[w];
    const float inv = 1.0f / sum;

#pragma unroll
    for (int i = 0; i < 4; i++) {
        v[i].x *= inv; v[i].y *= inv; v[i].z *= inv; v[i].w *= inv;
        ((float4*)p)[tid + i * 256] = v[i];
    }
}

// ---------------------------------------------------------------------------
// Kernel 4: out_b = P_b @ V_b   (NN gemm, K = 4096)
// ---------------------------------------------------------------------------
__global__ void __launch_bounds__(256) pv_gemm(float* __restrict__ out) {
    const int z = blockIdx.z;
    const int bm = blockIdx.y * 128;
    const int bn = blockIdx.x * 128;
    const float* P = g_S + (long)z * SEQ * SEQ;
    const float* V = g_V + (long)z * SEQ * DIM;
    float* O = out + (long)z * SEQ * DIM;

    float acc[8][8];
    gemm_tile<false>(P, SEQ, V, DIM, SEQ, bm, bn, acc);

    const int ty = threadIdx.x >> 4;
    const int tx = threadIdx.x & 15;
#pragma unroll
    for (int i = 0; i < 8; i++) {
        const long rowoff = (long)(bm + ty * 8 + i) * DIM;
#pragma unroll
        for (int j = 0; j < 8; j += 4) {
            float4 v;
            v.x = acc[i][j + 0];
            v.y = acc[i][j + 1];
            v.z = acc[i][j + 2];
            v.w = acc[i][j + 3];
            *(float4*)(O + rowoff + bn + tx * 8 + j) = v;
        }
    }
}

// ---------------------------------------------------------------------------
extern "C" void kernel_launch(void* const* d_in, const int* in_sizes, int n_in,
                              void* d_out, int out_size) {
    // Identify inputs by element count (robust to metadata ordering).
    const float* x1 = nullptr;    // 16,777,216
    const float* W = nullptr;     //  3,145,728
    const float* bias = nullptr;  //      3,072
    for (int i = 0; i < n_in; i++) {
        if (in_sizes[i] == BATCH * SEQ * DIM) x1 = (const float*)d_in[i];
        else if (in_sizes[i] == QKVN * DIM)   W = (const float*)d_in[i];
        else if (in_sizes[i] == QKVN)         bias = (const float*)d_in[i];
    }
    float* out = (float*)d_out;

    dim3 blk(256);
    // 1) QKV projection: grid (3072/128, 16384/128)
    qkv_gemm<<<dim3(QKVN / 128, (BATCH * SEQ) / 128), blk>>>(x1, W, bias);
    // 2) scores per batch: grid (4096/128, 4096/128, 4)
    scores_gemm<<<dim3(SEQ / 128, SEQ / 128, BATCH), blk>>>();
    // 3) softmax: one block per row
    softmax_kernel<<<BATCH * SEQ, blk>>>();
    // 4) P @ V: grid (1024/128, 4096/128, 4)
    pv_gemm<<<dim3(DIM / 128, SEQ / 128, BATCH), blk>>>(out);
}

// round 3
// speedup vs baseline: 3.2065x; 3.2065x over previous
#include <cuda_runtime.h>
#include <cuda_bf16.h>
#include <stdint.h>

typedef __nv_bfloat16 bf16;

#define BATCH 4
#define SEQ   4096
#define DIM   1024
#define QKVN  3072

// CTA tile
#define TM 128
#define TN 128
#define KC 64
#define PITCH 132   // fp32 stage pitch

// smem stage layout (per stage: 4 tiles of 128x64 bf16 = 16KB each)
#define STAGE_BYTES (64*1024)
#define OFF_AHI 0
#define OFF_ALO (16*1024)
#define OFF_BHI (32*1024)
#define OFF_BLO (48*1024)
#define SMEM_BYTES (2*STAGE_BYTES)   // 128 KB

#define NELT_X ((long)BATCH*SEQ*DIM)   // 16,777,216
#define NELT_W ((long)QKVN*DIM)        //  3,145,728
#define NELT_S ((long)BATCH*SEQ*SEQ)   // 67,108,864

// -------- scratch (device globals; no allocations allowed) --------
__device__ bf16 g_xhi[NELT_X], g_xlo[NELT_X];
__device__ bf16 g_Whi[NELT_W], g_Wlo[NELT_W];
__device__ bf16 g_Qhi[NELT_X], g_Qlo[NELT_X];
__device__ bf16 g_Khi[NELT_X], g_Klo[NELT_X];
__device__ bf16 g_Vthi[NELT_X], g_Vtlo[NELT_X];  // [B][DIM][SEQ] (V transposed)
__device__ float g_S[NELT_S];
__device__ bf16 g_Phi[NELT_S], g_Plo[NELT_S];

extern __shared__ char dynsmem[];

// ---------------- helpers ----------------
__device__ __forceinline__ uint32_t cvta_smem(const void* p) {
    uint32_t a;
    asm("{ .reg .u64 t; cvta.to.shared.u64 t, %1; cvt.u32.u64 %0, t; }" : "=r"(a) : "l"(p));
    return a;
}
__device__ __forceinline__ void cp16(uint32_t s, const void* g) {
    asm volatile("cp.async.cg.shared.global [%0], [%1], 16;" :: "r"(s), "l"(g));
}
__device__ __forceinline__ void cp_commit() { asm volatile("cp.async.commit_group;" ::: "memory"); }
template <int N> __device__ __forceinline__ void cp_wait() {
    asm volatile("cp.async.wait_group %0;" :: "n"(N) : "memory");
}
__device__ __forceinline__ uint32_t swz(uint32_t off) { return off ^ ((off >> 3) & 0x70); }

__device__ __forceinline__ void ldsm4(uint32_t& r0, uint32_t& r1, uint32_t& r2, uint32_t& r3,
                                      uint32_t addr) {
    asm volatile("ldmatrix.sync.aligned.m8n8.x4.shared.b16 {%0,%1,%2,%3}, [%4];"
                 : "=r"(r0), "=r"(r1), "=r"(r2), "=r"(r3) : "r"(addr));
}
__device__ __forceinline__ void mma16816(float* c, const uint32_t* a, const uint32_t* b) {
    asm volatile(
        "mma.sync.aligned.m16n8k16.row.col.f32.bf16.bf16.f32 "
        "{%0,%1,%2,%3}, {%4,%5,%6,%7}, {%8,%9}, {%0,%1,%2,%3};"
        : "+f"(c[0]), "+f"(c[1]), "+f"(c[2]), "+f"(c[3])
        : "r"(a[0]), "r"(a[1]), "r"(a[2]), "r"(a[3]), "r"(b[0]), "r"(b[1]));
}
__device__ __forceinline__ void split2(float a, float b, uint32_t& hu, uint32_t& lu) {
    bf16 ha = __float2bfloat16(a), hb = __float2bfloat16(b);
    bf16 la = __float2bfloat16(a - __bfloat162float(ha));
    bf16 lb = __float2bfloat16(b - __bfloat162float(hb));
    __nv_bfloat162 H; H.x = ha; H.y = hb;
    __nv_bfloat162 L; L.x = la; L.y = lb;
    hu = *reinterpret_cast<uint32_t*>(&H);
    lu = *reinterpret_cast<uint32_t*>(&L);
}

// load [128 x 64] bf16 K-major tile into SW128-swizzled smem (16B cp.async chunks)
__device__ __forceinline__ void load_tile(uint32_t sb, const bf16* __restrict__ src,
                                          long K, long row0, long k0) {
    const int tid = threadIdx.x;
#pragma unroll
    for (int i = 0; i < 4; i++) {
        const int idx = tid + i * 256;        // 0..1023
        const int r = idx >> 3, ch = idx & 7;
        const uint32_t off = swz((uint32_t)(r * 128 + ch * 16));
        cp16(sb + off, src + (row0 + r) * K + k0 + ch * 8);
    }
}

// ----------------------------------------------------------------------------
// Core: C[128,128] = sum_K (Ahi+Alo)[bm..,:] * (Bhi+Blo)[bn..,:]^T  (bf16x3)
// Result left in fp32 smem stage: stage[row*PITCH + col].
// ----------------------------------------------------------------------------
__device__ void gemm_core(const bf16* __restrict__ Ahi, const bf16* __restrict__ Alo,
                          const bf16* __restrict__ Bhi, const bf16* __restrict__ Blo,
                          long bm, long bn, int K) {
    const uint32_t smb = cvta_smem(dynsmem);
    const int tid = threadIdx.x;
    const int wid = tid >> 5, lane = tid & 31;
    const int wm = wid & 3;    // 0..3 : 32-row block
    const int wn = wid >> 2;   // 0..1 : 64-col block
    const int NIT = K / KC;

    float acc[2][8][4];
#pragma unroll
    for (int i = 0; i < 2; i++)
#pragma unroll
        for (int j = 0; j < 8; j++)
#pragma unroll
            for (int k = 0; k < 4; k++) acc[i][j][k] = 0.0f;

    // per-thread ldmatrix address parts (byte offsets within a 128x64 tile)
    const uint32_t aPart = (uint32_t)((lane & 15) * 128 + (lane >> 4) * 16);
    const uint32_t bPart = (uint32_t)((((lane & 7) + ((lane >> 4) << 3)) * 128) + ((lane >> 3) & 1) * 16);

    // prologue
    load_tile(smb + OFF_AHI, Ahi, K, bm, 0);
    load_tile(smb + OFF_ALO, Alo, K, bm, 0);
    load_tile(smb + OFF_BHI, Bhi, K, bn, 0);
    load_tile(smb + OFF_BLO, Blo, K, bn, 0);
    cp_commit();

    for (int it = 0; it < NIT; ++it) {
        const uint32_t cur = smb + (uint32_t)(it & 1) * STAGE_BYTES;
        if (it + 1 < NIT) {
            const uint32_t nxt = smb + (uint32_t)((it + 1) & 1) * STAGE_BYTES;
            const long k0 = (long)(it + 1) * KC;
            load_tile(nxt + OFF_AHI, Ahi, K, bm, k0);
            load_tile(nxt + OFF_ALO, Alo, K, bm, k0);
            load_tile(nxt + OFF_BHI, Bhi, K, bn, k0);
            load_tile(nxt + OFF_BLO, Blo, K, bn, k0);
            cp_commit();
            cp_wait<1>();
        } else {
            cp_wait<0>();
        }
        __syncthreads();

#pragma unroll
        for (int ks = 0; ks < KC / 16; ++ks) {
            uint32_t ah[2][4], al[2][4], bh[4][4], bl[4][4];
#pragma unroll
            for (int mt = 0; mt < 2; ++mt) {
                const uint32_t off = (uint32_t)((wm * 32 + mt * 16) * 128 + ks * 32) + aPart;
                ldsm4(ah[mt][0], ah[mt][1], ah[mt][2], ah[mt][3], cur + OFF_AHI + swz(off));
                ldsm4(al[mt][0], al[mt][1], al[mt][2], al[mt][3], cur + OFF_ALO + swz(off));
            }
#pragma unroll
            for (int nt = 0; nt < 4; ++nt) {
                const uint32_t off = (uint32_t)((wn * 64 + nt * 16) * 128 + ks * 32) + bPart;
                ldsm4(bh[nt][0], bh[nt][1], bh[nt][2], bh[nt][3], cur + OFF_BHI + swz(off));
                ldsm4(bl[nt][0], bl[nt][1], bl[nt][2], bl[nt][3], cur + OFF_BLO + swz(off));
            }
            // hi*hi
#pragma unroll
            for (int mt = 0; mt < 2; ++mt)
#pragma unroll
                for (int nt = 0; nt < 4; ++nt) {
                    mma16816(acc[mt][nt * 2],     ah[mt], &bh[nt][0]);
                    mma16816(acc[mt][nt * 2 + 1], ah[mt], &bh[nt][2]);
                }
            // hi*lo
#pragma unroll
            for (int mt = 0; mt < 2; ++mt)
#pragma unroll
                for (int nt = 0; nt < 4; ++nt) {
                    mma16816(acc[mt][nt * 2],     ah[mt], &bl[nt][0]);
                    mma16816(acc[mt][nt * 2 + 1], ah[mt], &bl[nt][2]);
                }
            // lo*hi
#pragma unroll
            for (int mt = 0; mt < 2; ++mt)
#pragma unroll
                for (int nt = 0; nt < 4; ++nt) {
                    mma16816(acc[mt][nt * 2],     al[mt], &bh[nt][0]);
                    mma16816(acc[mt][nt * 2 + 1], al[mt], &bh[nt][2]);
                }
        }
        __syncthreads();
    }

    // accums -> fp32 smem stage (buffers are dead now)
    float* stage = (float*)dynsmem;
    const int r0 = wm * 32 + (lane >> 2);
    const int c0 = wn * 64 + (lane & 3) * 2;
#pragma unroll
    for (int mt = 0; mt < 2; ++mt)
#pragma unroll
        for (int nt8 = 0; nt8 < 8; ++nt8) {
            const int r = r0 + mt * 16, c = c0 + nt8 * 8;
            *(float2*)&stage[r * PITCH + c] = make_float2(acc[mt][nt8][0], acc[mt][nt8][1]);
            *(float2*)&stage[(r + 8) * PITCH + c] = make_float2(acc[mt][nt8][2], acc[mt][nt8][3]);
        }
    __syncthreads();
}

// ---------------- Kernel: split fp32 -> (hi, lo) bf16 ----------------
__global__ void __launch_bounds__(256) convert_split(const float* __restrict__ in, int mode) {
    bf16* hi = mode ? g_Whi : g_xhi;
    bf16* lo = mode ? g_Wlo : g_xlo;
    const long i = (long)blockIdx.x * 256 + threadIdx.x;
    float4 v = ((const float4*)in)[i];
    uint2 H, L;
    split2(v.x, v.y, H.x, L.x);
    split2(v.z, v.w, H.y, L.y);
    *(uint2*)(hi + i * 4) = H;
    *(uint2*)(lo + i * 4) = L;
}

// ---------------- Kernel 1: QKV projection ----------------
__global__ void __launch_bounds__(256, 1) qkv_gemm_tc(const float* __restrict__ bias) {
    const long bm = (long)blockIdx.y * TM;
    const long bn = (long)blockIdx.x * TN;
    gemm_core(g_xhi, g_xlo, g_Whi, g_Wlo, bm, bn, DIM);

    float* stage = (float*)dynsmem;
    const int tid = threadIdx.x;
    const int sel = (int)(bn >> 10);        // 0:Q 1:K 2:V
    const long nc0 = bn & 1023;
    if (sel < 2) {
        bf16* Hi = sel ? g_Khi : g_Qhi;
        bf16* Lo = sel ? g_Klo : g_Qlo;
        for (int idx = tid; idx < TM * TN / 2; idx += 256) {
            const int row = idx >> 6, col = (idx & 63) * 2;
            const float v0 = stage[row * PITCH + col]     + bias[bn + col];
            const float v1 = stage[row * PITCH + col + 1] + bias[bn + col + 1];
            uint32_t H, L;
            split2(v0, v1, H, L);
            const long o = (bm + row) * DIM + nc0 + col;
            *(uint32_t*)(Hi + o) = H;
            *(uint32_t*)(Lo + o) = L;
        }
    } else {
        // V: write transposed Vt[b][n'][s] (consecutive tid -> consecutive s: coalesced)
        const long b = bm >> 12, s0 = bm & 4095;
        for (int idx = tid; idx < TM * TN; idx += 256) {
            const int row = idx & 127, col = idx >> 7;
            const float v = stage[row * PITCH + col] + bias[bn + col];
            const bf16 h = __float2bfloat16(v);
            const bf16 l = __float2bfloat16(v - __bfloat162float(h));
            const long o = (b * DIM + nc0 + col) * SEQ + s0 + row;
            g_Vthi[o] = h;
            g_Vtlo[o] = l;
        }
    }
}

// ---------------- Kernel 2: scores S = (Q K^T)/32 ----------------
__global__ void __launch_bounds__(256, 1) scores_gemm_tc() {
    const int z = blockIdx.z;
    const long bm = (long)blockIdx.y * TM;
    const long bn = (long)blockIdx.x * TN;
    const long qo = (long)z * SEQ * DIM;
    gemm_core(g_Qhi + qo, g_Qlo + qo, g_Khi + qo, g_Klo + qo, bm, bn, DIM);

    float* stage = (float*)dynsmem;
    float* Sp = g_S + (long)z * SEQ * SEQ;
    const float scale = 0.03125f;
    const int tid = threadIdx.x;
    for (int idx = tid; idx < TM * TN / 2; idx += 256) {
        const int row = idx >> 6, col = (idx & 63) * 2;
        float2 v;
        v.x = stage[row * PITCH + col] * scale;
        v.y = stage[row * PITCH + col + 1] * scale;
        *(float2*)(Sp + (bm + row) * SEQ + bn + col) = v;
    }
}

// ---------------- Kernel 3: row softmax + split to bf16 hi/lo ----------------
__global__ void __launch_bounds__(256) softmax_kernel() {
    const long row = blockIdx.x;
    const float* p = g_S + row * (long)SEQ;
    const int tid = threadIdx.x;
    const int warp = tid >> 5, lane = tid & 31;
    __shared__ float red[8];

    float4 v[4];
    float m = -3.402823466e38f;
#pragma unroll
    for (int i = 0; i < 4; i++) {
        v[i] = ((const float4*)p)[tid + i * 256];
        m = fmaxf(m, fmaxf(fmaxf(v[i].x, v[i].y), fmaxf(v[i].z, v[i].w)));
    }
#pragma unroll
    for (int o = 16; o > 0; o >>= 1) m = fmaxf(m, __shfl_xor_sync(0xffffffffu, m, o));
    if (lane == 0) red[warp] = m;
    __syncthreads();
    m = red[0];
#pragma unroll
    for (int w = 1; w < 8; w++) m = fmaxf(m, red[w]);
    __syncthreads();

    float sum = 0.0f;
#pragma unroll
    for (int i = 0; i < 4; i++) {
        v[i].x = __expf(v[i].x - m);
        v[i].y = __expf(v[i].y - m);
        v[i].z = __expf(v[i].z - m);
        v[i].w = __expf(v[i].w - m);
        sum += v[i].x + v[i].y + v[i].z + v[i].w;
    }
#pragma unroll
    for (int o = 16; o > 0; o >>= 1) sum += __shfl_xor_sync(0xffffffffu, sum, o);
    if (lane == 0) red[warp] = sum;
    __syncthreads();
    sum = red[0];
#pragma unroll
    for (int w = 1; w < 8; w++) sum += red[w];
    const float inv = 1.0f / sum;

#pragma unroll
    for (int i = 0; i < 4; i++) {
        const float a = v[i].x * inv, b = v[i].y * inv, c = v[i].z * inv, d = v[i].w * inv;
        uint2 H, L;
        split2(a, b, H.x, L.x);
        split2(c, d, H.y, L.y);
        const long o = row * (long)SEQ + (long)(tid + i * 256) * 4;
        *(uint2*)(g_Phi + o) = H;
        *(uint2*)(g_Plo + o) = L;
    }
}

// ---------------- Kernel 4: out = P @ V ----------------
__global__ void __launch_bounds__(256, 1) pv_gemm_tc(float* __restrict__ out) {
    const int z = blockIdx.z;
    const long bm = (long)blockIdx.y * TM;
    const long bn = (long)blockIdx.x * TN;
    const long po = (long)z * SEQ * SEQ;
    const long vo = (long)z * DIM * SEQ;
    gemm_core(g_Phi + po, g_Plo + po, g_Vthi + vo, g_Vtlo + vo, bm, bn, SEQ);

    float* stage = (float*)dynsmem;
    float* O = out + (long)z * SEQ * DIM;
    const int tid = threadIdx.x;
    for (int idx = tid; idx < TM * TN / 2; idx += 256) {
        const int row = idx >> 6, col = (idx & 63) * 2;
        float2 v;
        v.x = stage[row * PITCH + col];
        v.y = stage[row * PITCH + col + 1];
        *(float2*)(O + (bm + row) * DIM + bn + col) = v;
    }
}

// ---------------------------------------------------------------------------
extern "C" void kernel_launch(void* const* d_in, const int* in_sizes, int n_in,
                              void* d_out, int out_size) {
    const float* x1 = nullptr;
    const float* W = nullptr;
    const float* bias = nullptr;
    for (int i = 0; i < n_in; i++) {
        if (in_sizes[i] == (int)(BATCH * SEQ * DIM)) x1 = (const float*)d_in[i];
        else if (in_sizes[i] == (int)(QKVN * DIM))   W = (const float*)d_in[i];
        else if (in_sizes[i] == QKVN)                bias = (const float*)d_in[i];
    }
    float* out = (float*)d_out;

    cudaFuncSetAttribute(qkv_gemm_tc, cudaFuncAttributeMaxDynamicSharedMemorySize, SMEM_BYTES);
    cudaFuncSetAttribute(scores_gemm_tc, cudaFuncAttributeMaxDynamicSharedMemorySize, SMEM_BYTES);
    cudaFuncSetAttribute(pv_gemm_tc, cudaFuncAttributeMaxDynamicSharedMemorySize, SMEM_BYTES);

    convert_split<<<NELT_X / 1024, 256>>>(x1, 0);
    convert_split<<<NELT_W / 1024, 256>>>(W, 1);
    qkv_gemm_tc<<<dim3(QKVN / TN, (BATCH * SEQ) / TM), 256, SMEM_BYTES>>>(bias);
    scores_gemm_tc<<<dim3(SEQ / TN, SEQ / TM, BATCH), 256, SMEM_BYTES>>>();
    softmax_kernel<<<BATCH * SEQ, 256>>>();
    pv_gemm_tc<<<dim3(DIM / TN, SEQ / TM, BATCH), 256, SMEM_BYTES>>>(out);
}

// round 4
// speedup vs baseline: 4.3405x; 1.3537x over previous
#include <cuda_runtime.h>
#include <cuda_fp16.h>
#include <stdint.h>

#define BATCH 4
#define SEQ   4096
#define DIM   1024
#define QKVN  3072

// CTA tile
#define TM 128
#define TN 128
#define KC 64
#define PITCH 132   // fp32 stage pitch

#define TILE_BYTES (16*1024)          // 128x64 f16 tile
#define OFF_AHI 0
#define OFF_ALO (16*1024)
#define OFF_BHI (32*1024)
#define OFF_BLO (48*1024)

#define NELT_X ((long)BATCH*SEQ*DIM)   // 16,777,216
#define NELT_W ((long)QKVN*DIM)        //  3,145,728
#define NELT_S ((long)BATCH*SEQ*SEQ)   // 67,108,864

// -------- scratch (device globals; no allocations allowed) --------
__device__ __half g_xhi[NELT_X], g_xlo[NELT_X];
__device__ __half g_Whi[NELT_W], g_Wlo[NELT_W];
__device__ __half g_Qhi[NELT_X], g_Qlo[NELT_X];
__device__ __half g_Kh [NELT_X];                 // K: single f16
__device__ __half g_Vth[NELT_X];                 // V transposed [B][DIM][SEQ], single f16
__device__ __half g_Phi[NELT_S], g_Plo[NELT_S];  // unnormalized exp(scores)
__device__ float  g_rowsum[(long)BATCH * SEQ];

extern __shared__ char dynsmem[];

// ---------------- helpers ----------------
__device__ __forceinline__ uint32_t cvta_smem(const void* p) {
    uint32_t a;
    asm("{ .reg .u64 t; cvta.to.shared.u64 t, %1; cvt.u32.u64 %0, t; }" : "=r"(a) : "l"(p));
    return a;
}
__device__ __forceinline__ void cp16(uint32_t s, const void* g) {
    asm volatile("cp.async.cg.shared.global [%0], [%1], 16;" :: "r"(s), "l"(g));
}
__device__ __forceinline__ void cp_commit() { asm volatile("cp.async.commit_group;" ::: "memory"); }
template <int N> __device__ __forceinline__ void cp_wait() {
    asm volatile("cp.async.wait_group %0;" :: "n"(N) : "memory");
}
__device__ __forceinline__ uint32_t swz(uint32_t off) { return off ^ ((off >> 3) & 0x70); }

__device__ __forceinline__ void ldsm4(uint32_t& r0, uint32_t& r1, uint32_t& r2, uint32_t& r3,
                                      uint32_t addr) {
    asm volatile("ldmatrix.sync.aligned.m8n8.x4.shared.b16 {%0,%1,%2,%3}, [%4];"
                 : "=r"(r0), "=r"(r1), "=r"(r2), "=r"(r3) : "r"(addr));
}
__device__ __forceinline__ void mma16816(float* c, const uint32_t* a, const uint32_t* b) {
    asm volatile(
        "mma.sync.aligned.m16n8k16.row.col.f32.f16.f16.f32 "
        "{%0,%1,%2,%3}, {%4,%5,%6,%7}, {%8,%9}, {%0,%1,%2,%3};"
        : "+f"(c[0]), "+f"(c[1]), "+f"(c[2]), "+f"(c[3])
        : "r"(a[0]), "r"(a[1]), "r"(a[2]), "r"(a[3]), "r"(b[0]), "r"(b[1]));
}
// split fp32 pair into (hi,lo) f16 pairs, packed as half2 words
__device__ __forceinline__ void split2(float a, float b, uint32_t& hu, uint32_t& lu) {
    __half ha = __float2half_rn(a), hb = __float2half_rn(b);
    __half la = __float2half_rn(a - __half2float(ha));
    __half lb = __float2half_rn(b - __half2float(hb));
    __half2 H; H.x = ha; H.y = hb;
    __half2 L; L.x = la; L.y = lb;
    hu = *reinterpret_cast<uint32_t*>(&H);
    lu = *reinterpret_cast<uint32_t*>(&L);
}

// load [128 x 64] f16 K-major tile into SW128-swizzled smem (16B cp.async chunks)
__device__ __forceinline__ void load_tile(uint32_t sb, const __half* __restrict__ src,
                                          long K, long row0, long k0) {
    const int tid = threadIdx.x;
#pragma unroll
    for (int i = 0; i < 4; i++) {
        const int idx = tid + i * 256;        // 0..1023
        const int r = idx >> 3, ch = idx & 7;
        const uint32_t off = swz((uint32_t)(r * 128 + ch * 16));
        cp16(sb + off, src + (row0 + r) * K + k0 + ch * 8);
    }
}

// ----------------------------------------------------------------------------
// Core: C[128,128] = A * B^T with split-f16.
//  BLO=true : 3-product (Ah*Bh + Ah*Bl + Al*Bh)  — near-exact
//  BLO=false: 2-product (Ah*Bh + Al*Bh)          — B at f16 precision
// Result left in fp32 smem stage: stage[row*PITCH + col].
// ----------------------------------------------------------------------------
template <bool BLO>
__device__ void gemm_core(const __half* __restrict__ Ahi, const __half* __restrict__ Alo,
                          const __half* __restrict__ Bhi, const __half* __restrict__ Blo,
                          long bm, long bn, int K) {
    const uint32_t STAGE = BLO ? (64 * 1024) : (48 * 1024);
    const uint32_t smb = cvta_smem(dynsmem);
    const int tid = threadIdx.x;
    const int wid = tid >> 5, lane = tid & 31;
    const int wm = wid & 3;    // 0..3 : 32-row block
    const int wn = wid >> 2;   // 0..1 : 64-col block
    const int NIT = K / KC;

    float acc[2][8][4];
#pragma unroll
    for (int i = 0; i < 2; i++)
#pragma unroll
        for (int j = 0; j < 8; j++)
#pragma unroll
            for (int k = 0; k < 4; k++) acc[i][j][k] = 0.0f;

    const uint32_t aPart = (uint32_t)((lane & 15) * 128 + (lane >> 4) * 16);
    const uint32_t bPart = (uint32_t)((((lane & 7) + ((lane >> 4) << 3)) * 128) + ((lane >> 3) & 1) * 16);

    // prologue
    load_tile(smb + OFF_AHI, Ahi, K, bm, 0);
    load_tile(smb + OFF_ALO, Alo, K, bm, 0);
    load_tile(smb + OFF_BHI, Bhi, K, bn, 0);
    if (BLO) load_tile(smb + OFF_BLO, Blo, K, bn, 0);
    cp_commit();

    for (int it = 0; it < NIT; ++it) {
        const uint32_t cur = smb + (uint32_t)(it & 1) * STAGE;
        if (it + 1 < NIT) {
            const uint32_t nxt = smb + (uint32_t)((it + 1) & 1) * STAGE;
            const long k0 = (long)(it + 1) * KC;
            load_tile(nxt + OFF_AHI, Ahi, K, bm, k0);
            load_tile(nxt + OFF_ALO, Alo, K, bm, k0);
            load_tile(nxt + OFF_BHI, Bhi, K, bn, k0);
            if (BLO) load_tile(nxt + OFF_BLO, Blo, K, bn, k0);
            cp_commit();
            cp_wait<1>();
        } else {
            cp_wait<0>();
        }
        __syncthreads();

#pragma unroll
        for (int ks = 0; ks < KC / 16; ++ks) {
            uint32_t ah[2][4], al[2][4], bh[4][4];
#pragma unroll
            for (int mt = 0; mt < 2; ++mt) {
                const uint32_t off = (uint32_t)((wm * 32 + mt * 16) * 128 + ks * 32) + aPart;
                ldsm4(ah[mt][0], ah[mt][1], ah[mt][2], ah[mt][3], cur + OFF_AHI + swz(off));
                ldsm4(al[mt][0], al[mt][1], al[mt][2], al[mt][3], cur + OFF_ALO + swz(off));
            }
#pragma unroll
            for (int nt = 0; nt < 4; ++nt) {
                const uint32_t off = (uint32_t)((wn * 64 + nt * 16) * 128 + ks * 32) + bPart;
                ldsm4(bh[nt][0], bh[nt][1], bh[nt][2], bh[nt][3], cur + OFF_BHI + swz(off));
            }
            // hi*hi
#pragma unroll
            for (int mt = 0; mt < 2; ++mt)
#pragma unroll
                for (int nt = 0; nt < 4; ++nt) {
                    mma16816(acc[mt][nt * 2],     ah[mt], &bh[nt][0]);
                    mma16816(acc[mt][nt * 2 + 1], ah[mt], &bh[nt][2]);
                }
            // lo*hi
#pragma unroll
            for (int mt = 0; mt < 2; ++mt)
#pragma unroll
                for (int nt = 0; nt < 4; ++nt) {
                    mma16816(acc[mt][nt * 2],     al[mt], &bh[nt][0]);
                    mma16816(acc[mt][nt * 2 + 1], al[mt], &bh[nt][2]);
                }
            if (BLO) {
                uint32_t bl[4][4];
#pragma unroll
                for (int nt = 0; nt < 4; ++nt) {
                    const uint32_t off = (uint32_t)((wn * 64 + nt * 16) * 128 + ks * 32) + bPart;
                    ldsm4(bl[nt][0], bl[nt][1], bl[nt][2], bl[nt][3], cur + OFF_BLO + swz(off));
                }
#pragma unroll
                for (int mt = 0; mt < 2; ++mt)
#pragma unroll
                    for (int nt = 0; nt < 4; ++nt) {
                        mma16816(acc[mt][nt * 2],     ah[mt], &bl[nt][0]);
                        mma16816(acc[mt][nt * 2 + 1], ah[mt], &bl[nt][2]);
                    }
            }
        }
        __syncthreads();
    }

    // accums -> fp32 smem stage
    float* stage = (float*)dynsmem;
    const int r0 = wm * 32 + (lane >> 2);
    const int c0 = wn * 64 + (lane & 3) * 2;
#pragma unroll
    for (int mt = 0; mt < 2; ++mt)
#pragma unroll
        for (int nt8 = 0; nt8 < 8; ++nt8) {
            const int r = r0 + mt * 16, c = c0 + nt8 * 8;
            *(float2*)&stage[r * PITCH + c] = make_float2(acc[mt][nt8][0], acc[mt][nt8][1]);
            *(float2*)&stage[(r + 8) * PITCH + c] = make_float2(acc[mt][nt8][2], acc[mt][nt8][3]);
        }
    __syncthreads();
}

// ---------------- Kernel: split fp32 -> (hi, lo) f16 ----------------
__global__ void __launch_bounds__(256) convert_split(const float* __restrict__ in, int mode) {
    __half* hi = mode ? g_Whi : g_xhi;
    __half* lo = mode ? g_Wlo : g_xlo;
    const long i = (long)blockIdx.x * 256 + threadIdx.x;
    float4 v = ((const float4*)in)[i];
    uint2 H, L;
    split2(v.x, v.y, H.x, L.x);
    split2(v.z, v.w, H.y, L.y);
    *(uint2*)(hi + i * 4) = H;
    *(uint2*)(lo + i * 4) = L;
}

// ---------------- Kernel 1: QKV projection (3-product, near-exact) ----------------
__global__ void __launch_bounds__(256, 1) qkv_gemm_tc(const float* __restrict__ bias) {
    const long bm = (long)blockIdx.y * TM;
    const long bn = (long)blockIdx.x * TN;
    gemm_core<true>(g_xhi, g_xlo, g_Whi, g_Wlo, bm, bn, DIM);

    float* stage = (float*)dynsmem;
    const int tid = threadIdx.x;
    const int sel = (int)(bn >> 10);        // 0:Q 1:K 2:V
    const long nc0 = bn & 1023;
    if (sel == 0) {
        for (int idx = tid; idx < TM * TN / 2; idx += 256) {
            const int row = idx >> 6, col = (idx & 63) * 2;
            const float v0 = stage[row * PITCH + col]     + bias[bn + col];
            const float v1 = stage[row * PITCH + col + 1] + bias[bn + col + 1];
            uint32_t H, L;
            split2(v0, v1, H, L);
            const long o = (bm + row) * DIM + nc0 + col;
            *(uint32_t*)(g_Qhi + o) = H;
            *(uint32_t*)(g_Qlo + o) = L;
        }
    } else if (sel == 1) {
        for (int idx = tid; idx < TM * TN / 2; idx += 256) {
            const int row = idx >> 6, col = (idx & 63) * 2;
            const float v0 = stage[row * PITCH + col]     + bias[bn + col];
            const float v1 = stage[row * PITCH + col + 1] + bias[bn + col + 1];
            __half2 H; H.x = __float2half_rn(v0); H.y = __float2half_rn(v1);
            *(__half2*)(g_Kh + (bm + row) * DIM + nc0 + col) = H;
        }
    } else {
        // V: write transposed Vt[b][n'][s], single f16
        const long b = bm >> 12, s0 = bm & 4095;
        for (int idx = tid; idx < TM * TN; idx += 256) {
            const int row = idx & 127, col = idx >> 7;
            const float v = stage[row * PITCH + col] + bias[bn + col];
            g_Vth[(b * DIM + nc0 + col) * SEQ + s0 + row] = __float2half_rn(v);
        }
    }
}

// ---------------- Kernel 2: P̂ = exp((Q K^T)/32), unnormalized (2-product) ----------------
__global__ void __launch_bounds__(256, 2) scores_gemm_tc() {
    const int z = blockIdx.z;
    const long bm = (long)blockIdx.y * TM;
    const long bn = (long)blockIdx.x * TN;
    const long qo = (long)z * SEQ * DIM;
    gemm_core<false>(g_Qhi + qo, g_Qlo + qo, g_Kh + qo, nullptr, bm, bn, DIM);

    float* stage = (float*)dynsmem;
    const long so = (long)z * SEQ * SEQ;
    const int tid = threadIdx.x;
    for (int idx = tid; idx < TM * TN / 2; idx += 256) {
        const int row = idx >> 6, col = (idx & 63) * 2;
        const float e0 = __expf(stage[row * PITCH + col]     * 0.03125f);
        const float e1 = __expf(stage[row * PITCH + col + 1] * 0.03125f);
        uint32_t H, L;
        split2(e0, e1, H, L);
        const long o = so + (bm + row) * SEQ + bn + col;
        *(uint32_t*)(g_Phi + o) = H;
        *(uint32_t*)(g_Plo + o) = L;
    }
}

// ---------------- Kernel 3: row sums of P̂ (hi part; RN errors cancel) ----------------
__global__ void __launch_bounds__(256) rowsum_kernel() {
    const int warp = threadIdx.x >> 5, lane = threadIdx.x & 31;
    const long row = (long)blockIdx.x * 8 + warp;
    const uint4* p4 = (const uint4*)(g_Phi + row * SEQ);
    float s = 0.0f;
#pragma unroll
    for (int i = 0; i < 16; i++) {
        uint4 v = p4[lane + i * 32];
        const __half2* h = (const __half2*)&v;
#pragma unroll
        for (int j = 0; j < 4; j++) {
            float2 f = __half22float2(h[j]);
            s += f.x + f.y;
        }
    }
#pragma unroll
    for (int o = 16; o > 0; o >>= 1) s += __shfl_xor_sync(0xffffffffu, s, o);
    if (lane == 0) g_rowsum[row] = s;
}

// ---------------- Kernel 4: out = (P̂ @ V) / rowsum (2-product) ----------------
__global__ void __launch_bounds__(256, 2) pv_gemm_tc(float* __restrict__ out) {
    const int z = blockIdx.z;
    const long bm = (long)blockIdx.y * TM;
    const long bn = (long)blockIdx.x * TN;
    const long po = (long)z * SEQ * SEQ;
    const long vo = (long)z * DIM * SEQ;
    gemm_core<false>(g_Phi + po, g_Plo + po, g_Vth + vo, nullptr, bm, bn, SEQ);

    float* stage = (float*)dynsmem;
    float* O = out + (long)z * SEQ * DIM;
    const float* rs = g_rowsum + (long)z * SEQ;
    const int tid = threadIdx.x;
    for (int idx = tid; idx < TM * TN / 2; idx += 256) {
        const int row = idx >> 6, col = (idx & 63) * 2;
        const float inv = 1.0f / rs[bm + row];
        float2 v;
        v.x = stage[row * PITCH + col] * inv;
        v.y = stage[row * PITCH + col + 1] * inv;
        *(float2*)(O + (bm + row) * DIM + bn + col) = v;
    }
}

// ---------------------------------------------------------------------------
extern "C" void kernel_launch(void* const* d_in, const int* in_sizes, int n_in,
                              void* d_out, int out_size) {
    const float* x1 = nullptr;
    const float* W = nullptr;
    const float* bias = nullptr;
    for (int i = 0; i < n_in; i++) {
        if (in_sizes[i] == (int)(BATCH * SEQ * DIM)) x1 = (const float*)d_in[i];
        else if (in_sizes[i] == (int)(QKVN * DIM))   W = (const float*)d_in[i];
        else if (in_sizes[i] == QKVN)                bias = (const float*)d_in[i];
    }
    float* out = (float*)d_out;

    cudaFuncSetAttribute(qkv_gemm_tc, cudaFuncAttributeMaxDynamicSharedMemorySize, 128 * 1024);
    cudaFuncSetAttribute(scores_gemm_tc, cudaFuncAttributeMaxDynamicSharedMemorySize, 96 * 1024);
    cudaFuncSetAttribute(pv_gemm_tc, cudaFuncAttributeMaxDynamicSharedMemorySize, 96 * 1024);

    convert_split<<<NELT_X / 1024, 256>>>(x1, 0);
    convert_split<<<NELT_W / 1024, 256>>>(W, 1);
    qkv_gemm_tc<<<dim3(QKVN / TN, (BATCH * SEQ) / TM), 256, 128 * 1024>>>(bias);
    scores_gemm_tc<<<dim3(SEQ / TN, SEQ / TM, BATCH), 256, 96 * 1024>>>();
    rowsum_kernel<<<BATCH * SEQ / 8, 256>>>();
    pv_gemm_tc<<<dim3(DIM / TN, SEQ / TM, BATCH), 256, 96 * 1024>>>(out);
}

// round 5
// speedup vs baseline: 5.9972x; 1.3817x over previous
#include <cuda_runtime.h>
#include <cuda_fp16.h>
#include <stdint.h>

#define BATCH 4
#define SEQ   4096
#define DIM   1024
#define QKVN  3072

// CTA tile
#define TM 128
#define TN 128
#define KC 64
#define PITCH 132   // fp32 stage pitch

#define NELT_X ((long)BATCH*SEQ*DIM)   // 16,777,216
#define NELT_W ((long)QKVN*DIM)        //  3,145,728
#define NELT_S ((long)BATCH*SEQ*SEQ)   // 67,108,864

// -------- scratch (device globals; no allocations allowed) --------
__device__ __half g_xhi[NELT_X], g_xlo[NELT_X];
__device__ __half g_Wh [NELT_W];                 // W: single f16
__device__ __half g_Qhi[NELT_X], g_Qlo[NELT_X];
__device__ __half g_Kh [NELT_X];                 // K: single f16
__device__ __half g_Vth[NELT_X];                 // V transposed [B][DIM][SEQ], single f16
__device__ __half g_Ph [NELT_S];                 // unnormalized exp(scores), single f16
__device__ float  g_rowsum[(long)BATCH * SEQ];

extern __shared__ char dynsmem[];

// ---------------- helpers ----------------
__device__ __forceinline__ uint32_t cvta_smem(const void* p) {
    uint32_t a;
    asm("{ .reg .u64 t; cvta.to.shared.u64 t, %1; cvt.u32.u64 %0, t; }" : "=r"(a) : "l"(p));
    return a;
}
__device__ __forceinline__ void cp16(uint32_t s, const void* g) {
    asm volatile("cp.async.cg.shared.global [%0], [%1], 16;" :: "r"(s), "l"(g));
}
__device__ __forceinline__ void cp_commit() { asm volatile("cp.async.commit_group;" ::: "memory"); }
template <int N> __device__ __forceinline__ void cp_wait() {
    asm volatile("cp.async.wait_group %0;" :: "n"(N) : "memory");
}
__device__ __forceinline__ uint32_t swz(uint32_t off) { return off ^ ((off >> 3) & 0x70); }

__device__ __forceinline__ void ldsm4(uint32_t& r0, uint32_t& r1, uint32_t& r2, uint32_t& r3,
                                      uint32_t addr) {
    asm volatile("ldmatrix.sync.aligned.m8n8.x4.shared.b16 {%0,%1,%2,%3}, [%4];"
                 : "=r"(r0), "=r"(r1), "=r"(r2), "=r"(r3) : "r"(addr));
}
__device__ __forceinline__ void mma16816(float* c, const uint32_t* a, const uint32_t* b) {
    asm volatile(
        "mma.sync.aligned.m16n8k16.row.col.f32.f16.f16.f32 "
        "{%0,%1,%2,%3}, {%4,%5,%6,%7}, {%8,%9}, {%0,%1,%2,%3};"
        : "+f"(c[0]), "+f"(c[1]), "+f"(c[2]), "+f"(c[3])
        : "r"(a[0]), "r"(a[1]), "r"(a[2]), "r"(a[3]), "r"(b[0]), "r"(b[1]));
}
__device__ __forceinline__ void split2(float a, float b, uint32_t& hu, uint32_t& lu) {
    __half ha = __float2half_rn(a), hb = __float2half_rn(b);
    __half la = __float2half_rn(a - __half2float(ha));
    __half lb = __float2half_rn(b - __half2float(hb));
    __half2 H; H.x = ha; H.y = hb;
    __half2 L; L.x = la; L.y = lb;
    hu = *reinterpret_cast<uint32_t*>(&H);
    lu = *reinterpret_cast<uint32_t*>(&L);
}

// load [128 x 64] f16 K-major tile into SW128-swizzled smem (16B cp.async chunks)
__device__ __forceinline__ void load_tile(uint32_t sb, const __half* __restrict__ src,
                                          long K, long row0, long k0) {
    const int tid = threadIdx.x;
#pragma unroll
    for (int i = 0; i < 4; i++) {
        const int idx = tid + i * 256;        // 0..1023
        const int r = idx >> 3, ch = idx & 7;
        const uint32_t off = swz((uint32_t)(r * 128 + ch * 16));
        cp16(sb + off, src + (row0 + r) * K + k0 + ch * 8);
    }
}

// ----------------------------------------------------------------------------
// gemm2: C = (Ah + Al) * Bh^T  (A split f16, B single f16; 2 MMA products)
// stage = 48KB (3 tiles), double buffered -> 96KB smem
// ----------------------------------------------------------------------------
__device__ void gemm2(const __half* __restrict__ Ahi, const __half* __restrict__ Alo,
                      const __half* __restrict__ Bh, long bm, long bn, int K) {
    const uint32_t STAGE = 48 * 1024;
    const uint32_t OA = 0, OL = 16 * 1024, OB = 32 * 1024;
    const uint32_t smb = cvta_smem(dynsmem);
    const int tid = threadIdx.x;
    const int wid = tid >> 5, lane = tid & 31;
    const int wm = wid & 3, wn = wid >> 2;
    const int NIT = K / KC;

    float acc[2][8][4];
#pragma unroll
    for (int i = 0; i < 2; i++)
#pragma unroll
        for (int j = 0; j < 8; j++)
#pragma unroll
            for (int k = 0; k < 4; k++) acc[i][j][k] = 0.0f;

    const uint32_t aPart = (uint32_t)((lane & 15) * 128 + (lane >> 4) * 16);
    const uint32_t bPart = (uint32_t)((((lane & 7) + ((lane >> 4) << 3)) * 128) + ((lane >> 3) & 1) * 16);

    load_tile(smb + OA, Ahi, K, bm, 0);
    load_tile(smb + OL, Alo, K, bm, 0);
    load_tile(smb + OB, Bh, K, bn, 0);
    cp_commit();

    for (int it = 0; it < NIT; ++it) {
        const uint32_t cur = smb + (uint32_t)(it & 1) * STAGE;
        if (it + 1 < NIT) {
            const uint32_t nxt = smb + (uint32_t)((it + 1) & 1) * STAGE;
            const long k0 = (long)(it + 1) * KC;
            load_tile(nxt + OA, Ahi, K, bm, k0);
            load_tile(nxt + OL, Alo, K, bm, k0);
            load_tile(nxt + OB, Bh, K, bn, k0);
            cp_commit();
            cp_wait<1>();
        } else {
            cp_wait<0>();
        }
        __syncthreads();

#pragma unroll
        for (int ks = 0; ks < KC / 16; ++ks) {
            uint32_t ah[2][4], al[2][4], bh[4][4];
#pragma unroll
            for (int mt = 0; mt < 2; ++mt) {
                const uint32_t off = (uint32_t)((wm * 32 + mt * 16) * 128 + ks * 32) + aPart;
                ldsm4(ah[mt][0], ah[mt][1], ah[mt][2], ah[mt][3], cur + OA + swz(off));
                ldsm4(al[mt][0], al[mt][1], al[mt][2], al[mt][3], cur + OL + swz(off));
            }
#pragma unroll
            for (int nt = 0; nt < 4; ++nt) {
                const uint32_t off = (uint32_t)((wn * 64 + nt * 16) * 128 + ks * 32) + bPart;
                ldsm4(bh[nt][0], bh[nt][1], bh[nt][2], bh[nt][3], cur + OB + swz(off));
            }
#pragma unroll
            for (int mt = 0; mt < 2; ++mt)
#pragma unroll
                for (int nt = 0; nt < 4; ++nt) {
                    mma16816(acc[mt][nt * 2],     ah[mt], &bh[nt][0]);
                    mma16816(acc[mt][nt * 2 + 1], ah[mt], &bh[nt][2]);
                }
#pragma unroll
            for (int mt = 0; mt < 2; ++mt)
#pragma unroll
                for (int nt = 0; nt < 4; ++nt) {
                    mma16816(acc[mt][nt * 2],     al[mt], &bh[nt][0]);
                    mma16816(acc[mt][nt * 2 + 1], al[mt], &bh[nt][2]);
                }
        }
        __syncthreads();
    }

    float* stage = (float*)dynsmem;
    const int r0 = wm * 32 + (lane >> 2);
    const int c0 = wn * 64 + (lane & 3) * 2;
#pragma unroll
    for (int mt = 0; mt < 2; ++mt)
#pragma unroll
        for (int nt8 = 0; nt8 < 8; ++nt8) {
            const int r = r0 + mt * 16, c = c0 + nt8 * 8;
            *(float2*)&stage[r * PITCH + c] = make_float2(acc[mt][nt8][0], acc[mt][nt8][1]);
            *(float2*)&stage[(r + 8) * PITCH + c] = make_float2(acc[mt][nt8][2], acc[mt][nt8][3]);
        }
    __syncthreads();
}

// ----------------------------------------------------------------------------
// gemm1: C = Ah * Bh^T  (both single f16; 1 MMA product)
// stage = 32KB (2 tiles), double buffered -> 64KB buffers (68KB smem for stage)
// ----------------------------------------------------------------------------
__device__ void gemm1(const __half* __restrict__ Ah, const __half* __restrict__ Bh,
                      long bm, long bn, int K) {
    const uint32_t STAGE = 32 * 1024;
    const uint32_t OA = 0, OB = 16 * 1024;
    const uint32_t smb = cvta_smem(dynsmem);
    const int tid = threadIdx.x;
    const int wid = tid >> 5, lane = tid & 31;
    const int wm = wid & 3, wn = wid >> 2;
    const int NIT = K / KC;

    float acc[2][8][4];
#pragma unroll
    for (int i = 0; i < 2; i++)
#pragma unroll
        for (int j = 0; j < 8; j++)
#pragma unroll
            for (int k = 0; k < 4; k++) acc[i][j][k] = 0.0f;

    const uint32_t aPart = (uint32_t)((lane & 15) * 128 + (lane >> 4) * 16);
    const uint32_t bPart = (uint32_t)((((lane & 7) + ((lane >> 4) << 3)) * 128) + ((lane >> 3) & 1) * 16);

    load_tile(smb + OA, Ah, K, bm, 0);
    load_tile(smb + OB, Bh, K, bn, 0);
    cp_commit();

    for (int it = 0; it < NIT; ++it) {
        const uint32_t cur = smb + (uint32_t)(it & 1) * STAGE;
        if (it + 1 < NIT) {
            const uint32_t nxt = smb + (uint32_t)((it + 1) & 1) * STAGE;
            const long k0 = (long)(it + 1) * KC;
            load_tile(nxt + OA, Ah, K, bm, k0);
            load_tile(nxt + OB, Bh, K, bn, k0);
            cp_commit();
            cp_wait<1>();
        } else {
            cp_wait<0>();
        }
        __syncthreads();

#pragma unroll
        for (int ks = 0; ks < KC / 16; ++ks) {
            uint32_t ah[2][4], bh[4][4];
#pragma unroll
            for (int mt = 0; mt < 2; ++mt) {
                const uint32_t off = (uint32_t)((wm * 32 + mt * 16) * 128 + ks * 32) + aPart;
                ldsm4(ah[mt][0], ah[mt][1], ah[mt][2], ah[mt][3], cur + OA + swz(off));
            }
#pragma unroll
            for (int nt = 0; nt < 4; ++nt) {
                const uint32_t off = (uint32_t)((wn * 64 + nt * 16) * 128 + ks * 32) + bPart;
                ldsm4(bh[nt][0], bh[nt][1], bh[nt][2], bh[nt][3], cur + OB + swz(off));
            }
#pragma unroll
            for (int mt = 0; mt < 2; ++mt)
#pragma unroll
                for (int nt = 0; nt < 4; ++nt) {
                    mma16816(acc[mt][nt * 2],     ah[mt], &bh[nt][0]);
                    mma16816(acc[mt][nt * 2 + 1], ah[mt], &bh[nt][2]);
                }
        }
        __syncthreads();
    }

    float* stage = (float*)dynsmem;
    const int r0 = wm * 32 + (lane >> 2);
    const int c0 = wn * 64 + (lane & 3) * 2;
#pragma unroll
    for (int mt = 0; mt < 2; ++mt)
#pragma unroll
        for (int nt8 = 0; nt8 < 8; ++nt8) {
            const int r = r0 + mt * 16, c = c0 + nt8 * 8;
            *(float2*)&stage[r * PITCH + c] = make_float2(acc[mt][nt8][0], acc[mt][nt8][1]);
            *(float2*)&stage[(r + 8) * PITCH + c] = make_float2(acc[mt][nt8][2], acc[mt][nt8][3]);
        }
    __syncthreads();
}

// ---------------- converts ----------------
__global__ void __launch_bounds__(256) convert_split_x(const float* __restrict__ in) {
    const long i = (long)blockIdx.x * 256 + threadIdx.x;
    float4 v = ((const float4*)in)[i];
    uint2 H, L;
    split2(v.x, v.y, H.x, L.x);
    split2(v.z, v.w, H.y, L.y);
    *(uint2*)(g_xhi + i * 4) = H;
    *(uint2*)(g_xlo + i * 4) = L;
}
__global__ void __launch_bounds__(256) convert_w(const float* __restrict__ in) {
    const long i = (long)blockIdx.x * 256 + threadIdx.x;
    float4 v = ((const float4*)in)[i];
    __half2 a, b;
    a.x = __float2half_rn(v.x); a.y = __float2half_rn(v.y);
    b.x = __float2half_rn(v.z); b.y = __float2half_rn(v.w);
    uint2 o;
    o.x = *reinterpret_cast<uint32_t*>(&a);
    o.y = *reinterpret_cast<uint32_t*>(&b);
    *(uint2*)(g_Wh + i * 4) = o;
}

// ---------------- Kernel 1: QKV projection (x split, W single) ----------------
__global__ void __launch_bounds__(256, 2) qkv_gemm_tc(const float* __restrict__ bias) {
    const long bm = (long)blockIdx.y * TM;
    const long bn = (long)blockIdx.x * TN;
    gemm2(g_xhi, g_xlo, g_Wh, bm, bn, DIM);

    float* stage = (float*)dynsmem;
    const int tid = threadIdx.x;
    const int sel = (int)(bn >> 10);        // 0:Q 1:K 2:V
    const long nc0 = bn & 1023;
    if (sel == 0) {
        for (int idx = tid; idx < TM * TN / 2; idx += 256) {
            const int row = idx >> 6, col = (idx & 63) * 2;
            const float v0 = stage[row * PITCH + col]     + bias[bn + col];
            const float v1 = stage[row * PITCH + col + 1] + bias[bn + col + 1];
            uint32_t H, L;
            split2(v0, v1, H, L);
            const long o = (bm + row) * DIM + nc0 + col;
            *(uint32_t*)(g_Qhi + o) = H;
            *(uint32_t*)(g_Qlo + o) = L;
        }
    } else if (sel == 1) {
        for (int idx = tid; idx < TM * TN / 2; idx += 256) {
            const int row = idx >> 6, col = (idx & 63) * 2;
            const float v0 = stage[row * PITCH + col]     + bias[bn + col];
            const float v1 = stage[row * PITCH + col + 1] + bias[bn + col + 1];
            __half2 H; H.x = __float2half_rn(v0); H.y = __float2half_rn(v1);
            *(__half2*)(g_Kh + (bm + row) * DIM + nc0 + col) = H;
        }
    } else {
        // V: write transposed Vt[b][n'][s], single f16
        const long b = bm >> 12, s0 = bm & 4095;
        for (int idx = tid; idx < TM * TN; idx += 256) {
            const int row = idx & 127, col = idx >> 7;
            const float v = stage[row * PITCH + col] + bias[bn + col];
            g_Vth[(b * DIM + nc0 + col) * SEQ + s0 + row] = __float2half_rn(v);
        }
    }
}

// ---------------- Kernel 2: P̂ = exp((Q K^T)/32), single f16 ----------------
__global__ void __launch_bounds__(256, 2) scores_gemm_tc() {
    const int z = blockIdx.z;
    const long bm = (long)blockIdx.y * TM;
    const long bn = (long)blockIdx.x * TN;
    const long qo = (long)z * SEQ * DIM;
    gemm2(g_Qhi + qo, g_Qlo + qo, g_Kh + qo, bm, bn, DIM);

    float* stage = (float*)dynsmem;
    const long so = (long)z * SEQ * SEQ;
    const int tid = threadIdx.x;
    for (int idx = tid; idx < TM * TN / 2; idx += 256) {
        const int row = idx >> 6, col = (idx & 63) * 2;
        const float e0 = __expf(stage[row * PITCH + col]     * 0.03125f);
        const float e1 = __expf(stage[row * PITCH + col + 1] * 0.03125f);
        __half2 H; H.x = __float2half_rn(e0); H.y = __float2half_rn(e1);
        *(__half2*)(g_Ph + so + (bm + row) * SEQ + bn + col) = H;
    }
}

// ---------------- Kernel 3: row sums of P̂ (same f16 values the MMA sees) ----------------
__global__ void __launch_bounds__(256) rowsum_kernel() {
    const int warp = threadIdx.x >> 5, lane = threadIdx.x & 31;
    const long row = (long)blockIdx.x * 8 + warp;
    const uint4* p4 = (const uint4*)(g_Ph + row * SEQ);
    float s = 0.0f;
#pragma unroll
    for (int i = 0; i < 16; i++) {
        uint4 v = p4[lane + i * 32];
        const __half2* h = (const __half2*)&v;
#pragma unroll
        for (int j = 0; j < 4; j++) {
            float2 f = __half22float2(h[j]);
            s += f.x + f.y;
        }
    }
#pragma unroll
    for (int o = 16; o > 0; o >>= 1) s += __shfl_xor_sync(0xffffffffu, s, o);
    if (lane == 0) g_rowsum[row] = s;
}

// ---------------- Kernel 4: out = (P̂ @ V) / rowsum (1-product) ----------------
__global__ void __launch_bounds__(256, 2) pv_gemm_tc(float* __restrict__ out) {
    const int z = blockIdx.z;
    const long bm = (long)blockIdx.y * TM;
    const long bn = (long)blockIdx.x * TN;
    const long po = (long)z * SEQ * SEQ;
    const long vo = (long)z * DIM * SEQ;
    gemm1(g_Ph + po, g_Vth + vo, bm, bn, SEQ);

    float* stage = (float*)dynsmem;
    float* O = out + (long)z * SEQ * DIM;
    const float* rs = g_rowsum + (long)z * SEQ;
    const int tid = threadIdx.x;
    for (int idx = tid; idx < TM * TN / 2; idx += 256) {
        const int row = idx >> 6, col = (idx & 63) * 2;
        const float inv = 1.0f / rs[bm + row];
        float2 v;
        v.x = stage[row * PITCH + col] * inv;
        v.y = stage[row * PITCH + col + 1] * inv;
        *(float2*)(O + (bm + row) * DIM + bn + col) = v;
    }
}

// ---------------------------------------------------------------------------
extern "C" void kernel_launch(void* const* d_in, const int* in_sizes, int n_in,
                              void* d_out, int out_size) {
    const float* x1 = nullptr;
    const float* W = nullptr;
    const float* bias = nullptr;
    for (int i = 0; i < n_in; i++) {
        if (in_sizes[i] == (int)(BATCH * SEQ * DIM)) x1 = (const float*)d_in[i];
        else if (in_sizes[i] == (int)(QKVN * DIM))   W = (const float*)d_in[i];
        else if (in_sizes[i] == QKVN)                bias = (const float*)d_in[i];
    }
    float* out = (float*)d_out;

    const int SM_QKV = 96 * 1024;   // 2x48KB stages (stage overlay 67.6KB fits)
    const int SM_PV  = 68 * 1024;   // 2x32KB stages + fp32 stage overlay 67.6KB

    cudaFuncSetAttribute(qkv_gemm_tc, cudaFuncAttributeMaxDynamicSharedMemorySize, SM_QKV);
    cudaFuncSetAttribute(scores_gemm_tc, cudaFuncAttributeMaxDynamicSharedMemorySize, SM_QKV);
    cudaFuncSetAttribute(pv_gemm_tc, cudaFuncAttributeMaxDynamicSharedMemorySize, SM_PV);

    convert_split_x<<<NELT_X / 1024, 256>>>(x1);
    convert_w<<<NELT_W / 1024, 256>>>(W);
    qkv_gemm_tc<<<dim3(QKVN / TN, (BATCH * SEQ) / TM), 256, SM_QKV>>>(bias);
    scores_gemm_tc<<<dim3(SEQ / TN, SEQ / TM, BATCH), 256, SM_QKV>>>();
    rowsum_kernel<<<BATCH * SEQ / 8, 256>>>();
    pv_gemm_tc<<<dim3(DIM / TN, SEQ / TM, BATCH), 256, SM_PV>>>(out);
}

// round 6
// speedup vs baseline: 7.3723x; 1.2293x over previous
#include <cuda_runtime.h>
#include <cuda_fp16.h>
#include <stdint.h>

#define BATCH 4
#define SEQ   4096
#define DIM   1024
#define QKVN  3072

// CTA tile
#define TM 128
#define TN 128
#define KC 64
#define PITCH 132   // fp32 stage pitch

#define NELT_X ((long)BATCH*SEQ*DIM)   // 16,777,216
#define NELT_W ((long)QKVN*DIM)        //  3,145,728
#define NELT_S ((long)BATCH*SEQ*SEQ)   // 67,108,864

// -------- scratch (device globals; no allocations allowed) --------
__device__ __half g_xhi[NELT_X], g_xlo[NELT_X];
__device__ __half g_Wh [NELT_W];                 // W: single f16
__device__ __half g_Qh [NELT_X];                 // Q: single f16
__device__ __half g_Kh [NELT_X];                 // K: single f16
__device__ __half g_Vth[NELT_X];                 // V transposed [B][DIM][SEQ]
__device__ __half g_Ph [NELT_S];                 // unnormalized exp(scores)
__device__ float  g_rowsum[(long)BATCH * SEQ];

extern __shared__ char dynsmem[];

// ---------------- helpers ----------------
__device__ __forceinline__ uint32_t cvta_smem(const void* p) {
    uint32_t a;
    asm("{ .reg .u64 t; cvta.to.shared.u64 t, %1; cvt.u32.u64 %0, t; }" : "=r"(a) : "l"(p));
    return a;
}
__device__ __forceinline__ void cp16(uint32_t s, const void* g) {
    asm volatile("cp.async.cg.shared.global [%0], [%1], 16;" :: "r"(s), "l"(g));
}
__device__ __forceinline__ void cp_commit() { asm volatile("cp.async.commit_group;" ::: "memory"); }
template <int N> __device__ __forceinline__ void cp_wait() {
    asm volatile("cp.async.wait_group %0;" :: "n"(N) : "memory");
}
__device__ __forceinline__ uint32_t swz(uint32_t off) { return off ^ ((off >> 3) & 0x70); }

__device__ __forceinline__ void ldsm4(uint32_t& r0, uint32_t& r1, uint32_t& r2, uint32_t& r3,
                                      uint32_t addr) {
    asm volatile("ldmatrix.sync.aligned.m8n8.x4.shared.b16 {%0,%1,%2,%3}, [%4];"
                 : "=r"(r0), "=r"(r1), "=r"(r2), "=r"(r3) : "r"(addr));
}
__device__ __forceinline__ void mma16816(float* c, const uint32_t* a, const uint32_t* b) {
    asm volatile(
        "mma.sync.aligned.m16n8k16.row.col.f32.f16.f16.f32 "
        "{%0,%1,%2,%3}, {%4,%5,%6,%7}, {%8,%9}, {%0,%1,%2,%3};"
        : "+f"(c[0]), "+f"(c[1]), "+f"(c[2]), "+f"(c[3])
        : "r"(a[0]), "r"(a[1]), "r"(a[2]), "r"(a[3]), "r"(b[0]), "r"(b[1]));
}
__device__ __forceinline__ void split2(float a, float b, uint32_t& hu, uint32_t& lu) {
    __half ha = __float2half_rn(a), hb = __float2half_rn(b);
    __half la = __float2half_rn(a - __half2float(ha));
    __half lb = __float2half_rn(b - __half2float(hb));
    __half2 H; H.x = ha; H.y = hb;
    __half2 L; L.x = la; L.y = lb;
    hu = *reinterpret_cast<uint32_t*>(&H);
    lu = *reinterpret_cast<uint32_t*>(&L);
}

// load [128 x 64] f16 K-major tile into SW128-swizzled smem (16B cp.async chunks)
__device__ __forceinline__ void load_tile(uint32_t sb, const __half* __restrict__ src,
                                          long K, long row0, long k0) {
    const int tid = threadIdx.x;
#pragma unroll
    for (int i = 0; i < 4; i++) {
        const int idx = tid + i * 256;        // 0..1023
        const int r = idx >> 3, ch = idx & 7;
        const uint32_t off = swz((uint32_t)(r * 128 + ch * 16));
        cp16(sb + off, src + (row0 + r) * K + k0 + ch * 8);
    }
}

// ----------------------------------------------------------------------------
// gemm1: C = Ah * Bh^T  (both single f16; 1 MMA product)
// 3-stage cp.async pipeline; stage = 32KB (2 tiles) -> 96KB smem
// ----------------------------------------------------------------------------
__device__ void gemm1(const __half* __restrict__ Ah, const __half* __restrict__ Bh,
                      long bm, long bn, int K) {
    const uint32_t STAGE = 32 * 1024;
    const uint32_t OA = 0, OB = 16 * 1024;
    const uint32_t smb = cvta_smem(dynsmem);
    const int tid = threadIdx.x;
    const int wid = tid >> 5, lane = tid & 31;
    const int wm = wid & 3, wn = wid >> 2;
    const int NIT = K / KC;   // >= 2 always here

    float acc[2][8][4];
#pragma unroll
    for (int i = 0; i < 2; i++)
#pragma unroll
        for (int j = 0; j < 8; j++)
#pragma unroll
            for (int k = 0; k < 4; k++) acc[i][j][k] = 0.0f;

    const uint32_t aPart = (uint32_t)((lane & 15) * 128 + (lane >> 4) * 16);
    const uint32_t bPart = (uint32_t)((((lane & 7) + ((lane >> 4) << 3)) * 128) + ((lane >> 3) & 1) * 16);

    // prologue: stages 0,1 (group ids 0,1)
    load_tile(smb + 0 * STAGE + OA, Ah, K, bm, 0);
    load_tile(smb + 0 * STAGE + OB, Bh, K, bn, 0);
    cp_commit();
    load_tile(smb + 1 * STAGE + OA, Ah, K, bm, KC);
    load_tile(smb + 1 * STAGE + OB, Bh, K, bn, KC);
    cp_commit();

    int stg = 0;             // = it % 3
    int nstg = 2;            // = (it+2) % 3
    for (int it = 0; it < NIT; ++it) {
        if (it + 2 < NIT) {
            const uint32_t nb = smb + (uint32_t)nstg * STAGE;
            const long k0 = (long)(it + 2) * KC;
            load_tile(nb + OA, Ah, K, bm, k0);
            load_tile(nb + OB, Bh, K, bn, k0);
        }
        cp_commit();          // always commit -> group id it+2
        cp_wait<2>();         // group it complete
        __syncthreads();

        const uint32_t cur = smb + (uint32_t)stg * STAGE;
#pragma unroll
        for (int ks = 0; ks < KC / 16; ++ks) {
            uint32_t ah[2][4], bh[4][4];
#pragma unroll
            for (int mt = 0; mt < 2; ++mt) {
                const uint32_t off = (uint32_t)((wm * 32 + mt * 16) * 128 + ks * 32) + aPart;
                ldsm4(ah[mt][0], ah[mt][1], ah[mt][2], ah[mt][3], cur + OA + swz(off));
            }
#pragma unroll
            for (int nt = 0; nt < 4; ++nt) {
                const uint32_t off = (uint32_t)((wn * 64 + nt * 16) * 128 + ks * 32) + bPart;
                ldsm4(bh[nt][0], bh[nt][1], bh[nt][2], bh[nt][3], cur + OB + swz(off));
            }
#pragma unroll
            for (int mt = 0; mt < 2; ++mt)
#pragma unroll
                for (int nt = 0; nt < 4; ++nt) {
                    mma16816(acc[mt][nt * 2],     ah[mt], &bh[nt][0]);
                    mma16816(acc[mt][nt * 2 + 1], ah[mt], &bh[nt][2]);
                }
        }
        __syncthreads();
        stg = (stg == 2) ? 0 : stg + 1;
        nstg = (nstg == 2) ? 0 : nstg + 1;
    }

    float* stage = (float*)dynsmem;
    const int r0 = wm * 32 + (lane >> 2);
    const int c0 = wn * 64 + (lane & 3) * 2;
#pragma unroll
    for (int mt = 0; mt < 2; ++mt)
#pragma unroll
        for (int nt8 = 0; nt8 < 8; ++nt8) {
            const int r = r0 + mt * 16, c = c0 + nt8 * 8;
            *(float2*)&stage[r * PITCH + c] = make_float2(acc[mt][nt8][0], acc[mt][nt8][1]);
            *(float2*)&stage[(r + 8) * PITCH + c] = make_float2(acc[mt][nt8][2], acc[mt][nt8][3]);
        }
    __syncthreads();
}

// ----------------------------------------------------------------------------
// gemm2: C = (Ah + Al) * Bh^T  (A split f16, B single; 2 MMA products)
// 2-stage; stage = 48KB (3 tiles) -> 96KB smem
// ----------------------------------------------------------------------------
__device__ void gemm2(const __half* __restrict__ Ahi, const __half* __restrict__ Alo,
                      const __half* __restrict__ Bh, long bm, long bn, int K) {
    const uint32_t STAGE = 48 * 1024;
    const uint32_t OA = 0, OL = 16 * 1024, OB = 32 * 1024;
    const uint32_t smb = cvta_smem(dynsmem);
    const int tid = threadIdx.x;
    const int wid = tid >> 5, lane = tid & 31;
    const int wm = wid & 3, wn = wid >> 2;
    const int NIT = K / KC;

    float acc[2][8][4];
#pragma unroll
    for (int i = 0; i < 2; i++)
#pragma unroll
        for (int j = 0; j < 8; j++)
#pragma unroll
            for (int k = 0; k < 4; k++) acc[i][j][k] = 0.0f;

    const uint32_t aPart = (uint32_t)((lane & 15) * 128 + (lane >> 4) * 16);
    const uint32_t bPart = (uint32_t)((((lane & 7) + ((lane >> 4) << 3)) * 128) + ((lane >> 3) & 1) * 16);

    load_tile(smb + OA, Ahi, K, bm, 0);
    load_tile(smb + OL, Alo, K, bm, 0);
    load_tile(smb + OB, Bh, K, bn, 0);
    cp_commit();

    for (int it = 0; it < NIT; ++it) {
        const uint32_t cur = smb + (uint32_t)(it & 1) * STAGE;
        if (it + 1 < NIT) {
            const uint32_t nxt = smb + (uint32_t)((it + 1) & 1) * STAGE;
            const long k0 = (long)(it + 1) * KC;
            load_tile(nxt + OA, Ahi, K, bm, k0);
            load_tile(nxt + OL, Alo, K, bm, k0);
            load_tile(nxt + OB, Bh, K, bn, k0);
            cp_commit();
            cp_wait<1>();
        } else {
            cp_wait<0>();
        }
        __syncthreads();

#pragma unroll
        for (int ks = 0; ks < KC / 16; ++ks) {
            uint32_t ah[2][4], al[2][4], bh[4][4];
#pragma unroll
            for (int mt = 0; mt < 2; ++mt) {
                const uint32_t off = (uint32_t)((wm * 32 + mt * 16) * 128 + ks * 32) + aPart;
                ldsm4(ah[mt][0], ah[mt][1], ah[mt][2], ah[mt][3], cur + OA + swz(off));
                ldsm4(al[mt][0], al[mt][1], al[mt][2], al[mt][3], cur + OL + swz(off));
            }
#pragma unroll
            for (int nt = 0; nt < 4; ++nt) {
                const uint32_t off = (uint32_t)((wn * 64 + nt * 16) * 128 + ks * 32) + bPart;
                ldsm4(bh[nt][0], bh[nt][1], bh[nt][2], bh[nt][3], cur + OB + swz(off));
            }
#pragma unroll
            for (int mt = 0; mt < 2; ++mt)
#pragma unroll
                for (int nt = 0; nt < 4; ++nt) {
                    mma16816(acc[mt][nt * 2],     ah[mt], &bh[nt][0]);
                    mma16816(acc[mt][nt * 2 + 1], ah[mt], &bh[nt][2]);
                }
#pragma unroll
            for (int mt = 0; mt < 2; ++mt)
#pragma unroll
                for (int nt = 0; nt < 4; ++nt) {
                    mma16816(acc[mt][nt * 2],     al[mt], &bh[nt][0]);
                    mma16816(acc[mt][nt * 2 + 1], al[mt], &bh[nt][2]);
                }
        }
        __syncthreads();
    }

    float* stage = (float*)dynsmem;
    const int r0 = wm * 32 + (lane >> 2);
    const int c0 = wn * 64 + (lane & 3) * 2;
#pragma unroll
    for (int mt = 0; mt < 2; ++mt)
#pragma unroll
        for (int nt8 = 0; nt8 < 8; ++nt8) {
            const int r = r0 + mt * 16, c = c0 + nt8 * 8;
            *(float2*)&stage[r * PITCH + c] = make_float2(acc[mt][nt8][0], acc[mt][nt8][1]);
            *(float2*)&stage[(r + 8) * PITCH + c] = make_float2(acc[mt][nt8][2], acc[mt][nt8][3]);
        }
    __syncthreads();
}

// ---------------- converts ----------------
__global__ void __launch_bounds__(256) convert_split_x(const float* __restrict__ in) {
    const long i = (long)blockIdx.x * 256 + threadIdx.x;
    float4 v = ((const float4*)in)[i];
    uint2 H, L;
    split2(v.x, v.y, H.x, L.x);
    split2(v.z, v.w, H.y, L.y);
    *(uint2*)(g_xhi + i * 4) = H;
    *(uint2*)(g_xlo + i * 4) = L;
}
__global__ void __launch_bounds__(256) convert_w(const float* __restrict__ in) {
    const long i = (long)blockIdx.x * 256 + threadIdx.x;
    float4 v = ((const float4*)in)[i];
    __half2 a, b;
    a.x = __float2half_rn(v.x); a.y = __float2half_rn(v.y);
    b.x = __float2half_rn(v.z); b.y = __float2half_rn(v.w);
    uint2 o;
    o.x = *reinterpret_cast<uint32_t*>(&a);
    o.y = *reinterpret_cast<uint32_t*>(&b);
    *(uint2*)(g_Wh + i * 4) = o;
}

// ---------------- Kernel 1: QKV projection (x split, W single) ----------------
__global__ void __launch_bounds__(256, 2) qkv_gemm_tc(const float* __restrict__ bias) {
    const long bm = (long)blockIdx.y * TM;
    const long bn = (long)blockIdx.x * TN;
    gemm2(g_xhi, g_xlo, g_Wh, bm, bn, DIM);

    float* stage = (float*)dynsmem;
    const int tid = threadIdx.x;
    const int sel = (int)(bn >> 10);        // 0:Q 1:K 2:V
    const long nc0 = bn & 1023;
    if (sel < 2) {
        __half* dst = sel ? g_Kh : g_Qh;
        for (int idx = tid; idx < TM * TN / 2; idx += 256) {
            const int row = idx >> 6, col = (idx & 63) * 2;
            const float v0 = stage[row * PITCH + col]     + bias[bn + col];
            const float v1 = stage[row * PITCH + col + 1] + bias[bn + col + 1];
            __half2 H; H.x = __float2half_rn(v0); H.y = __float2half_rn(v1);
            *(__half2*)(dst + (bm + row) * DIM + nc0 + col) = H;
        }
    } else {
        // V: write transposed Vt[b][n'][s], single f16
        const long b = bm >> 12, s0 = bm & 4095;
        for (int idx = tid; idx < TM * TN; idx += 256) {
            const int row = idx & 127, col = idx >> 7;
            const float v = stage[row * PITCH + col] + bias[bn + col];
            g_Vth[(b * DIM + nc0 + col) * SEQ + s0 + row] = __float2half_rn(v);
        }
    }
}

// ---------------- Kernel 2: P̂ = exp((Q K^T)/32), single f16 (1-product) ----------------
__global__ void __launch_bounds__(256, 2) scores_gemm_tc() {
    const int z = blockIdx.z;
    const long bm = (long)blockIdx.y * TM;
    const long bn = (long)blockIdx.x * TN;
    const long qo = (long)z * SEQ * DIM;
    gemm1(g_Qh + qo, g_Kh + qo, bm, bn, DIM);

    float* stage = (float*)dynsmem;
    const long so = (long)z * SEQ * SEQ;
    const int tid = threadIdx.x;
    for (int idx = tid; idx < TM * TN / 2; idx += 256) {
        const int row = idx >> 6, col = (idx & 63) * 2;
        const float e0 = __expf(stage[row * PITCH + col]     * 0.03125f);
        const float e1 = __expf(stage[row * PITCH + col + 1] * 0.03125f);
        __half2 H; H.x = __float2half_rn(e0); H.y = __float2half_rn(e1);
        *(__half2*)(g_Ph + so + (bm + row) * SEQ + bn + col) = H;
    }
}

// ---------------- Kernel 3: row sums of P̂ (same f16 values the MMA sees) ----------------
__global__ void __launch_bounds__(256) rowsum_kernel() {
    const int warp = threadIdx.x >> 5, lane = threadIdx.x & 31;
    const long row = (long)blockIdx.x * 8 + warp;
    const uint4* p4 = (const uint4*)(g_Ph + row * SEQ);
    float s = 0.0f;
#pragma unroll
    for (int i = 0; i < 16; i++) {
        uint4 v = p4[lane + i * 32];
        const __half2* h = (const __half2*)&v;
#pragma unroll
        for (int j = 0; j < 4; j++) {
            float2 f = __half22float2(h[j]);
            s += f.x + f.y;
        }
    }
#pragma unroll
    for (int o = 16; o > 0; o >>= 1) s += __shfl_xor_sync(0xffffffffu, s, o);
    if (lane == 0) g_rowsum[row] = s;
}

// ---------------- Kernel 4: out = (P̂ @ V) / rowsum (1-product) ----------------
__global__ void __launch_bounds__(256, 2) pv_gemm_tc(float* __restrict__ out) {
    const int z = blockIdx.z;
    const long bm = (long)blockIdx.y * TM;
    const long bn = (long)blockIdx.x * TN;
    const long po = (long)z * SEQ * SEQ;
    const long vo = (long)z * DIM * SEQ;
    gemm1(g_Ph + po, g_Vth + vo, bm, bn, SEQ);

    float* stage = (float*)dynsmem;
    float* O = out + (long)z * SEQ * DIM;
    const float* rs = g_rowsum + (long)z * SEQ;
    const int tid = threadIdx.x;
    for (int idx = tid; idx < TM * TN / 2; idx += 256) {
        const int row = idx >> 6, col = (idx & 63) * 2;
        const float inv = 1.0f / rs[bm + row];
        float2 v;
        v.x = stage[row * PITCH + col] * inv;
        v.y = stage[row * PITCH + col + 1] * inv;
        *(float2*)(O + (bm + row) * DIM + bn + col) = v;
    }
}

// ---------------------------------------------------------------------------
extern "C" void kernel_launch(void* const* d_in, const int* in_sizes, int n_in,
                              void* d_out, int out_size) {
    const float* x1 = nullptr;
    const float* W = nullptr;
    const float* bias = nullptr;
    for (int i = 0; i < n_in; i++) {
        if (in_sizes[i] == (int)(BATCH * SEQ * DIM)) x1 = (const float*)d_in[i];
        else if (in_sizes[i] == (int)(QKVN * DIM))   W = (const float*)d_in[i];
        else if (in_sizes[i] == QKVN)                bias = (const float*)d_in[i];
    }
    float* out = (float*)d_out;

    const int SM_BYTES = 96 * 1024;   // gemm2: 2x48KB | gemm1: 3x32KB; epilogue overlay 67.6KB

    cudaFuncSetAttribute(qkv_gemm_tc, cudaFuncAttributeMaxDynamicSharedMemorySize, SM_BYTES);
    cudaFuncSetAttribute(scores_gemm_tc, cudaFuncAttributeMaxDynamicSharedMemorySize, SM_BYTES);
    cudaFuncSetAttribute(pv_gemm_tc, cudaFuncAttributeMaxDynamicSharedMemorySize, SM_BYTES);

    convert_split_x<<<NELT_X / 1024, 256>>>(x1);
    convert_w<<<NELT_W / 1024, 256>>>(W);
    qkv_gemm_tc<<<dim3(QKVN / TN, (BATCH * SEQ) / TM), 256, SM_BYTES>>>(bias);
    scores_gemm_tc<<<dim3(SEQ / TN, SEQ / TM, BATCH), 256, SM_BYTES>>>();
    rowsum_kernel<<<BATCH * SEQ / 8, 256>>>();
    pv_gemm_tc<<<dim3(DIM / TN, SEQ / TM, BATCH), 256, SM_BYTES>>>(out);
}

// round 8
// speedup vs baseline: 8.9134x; 1.2090x over previous
#include <cuda_runtime.h>
#include <cuda_fp16.h>
#include <stdint.h>

#define BATCH 4
#define SEQ   4096
#define DIM   1024
#define QKVN  3072

// CTA tile
#define TM 128
#define TN 128
#define KC 64
#define PITCH 132   // fp32 stage pitch

#define NELT_X ((long)BATCH*SEQ*DIM)   // 16,777,216
#define NELT_W ((long)QKVN*DIM)        //  3,145,728
#define NELT_S ((long)BATCH*SEQ*SEQ)   // 67,108,864

// -------- scratch (device globals; no allocations allowed) --------
__device__ __half g_xh [NELT_X];                 // x: single f16
__device__ __half g_Wh [NELT_W];                 // W: single f16
__device__ __half g_Qh [NELT_X];                 // Q: single f16
__device__ __half g_Kh [NELT_X];                 // K: single f16
__device__ __half g_Vth[NELT_X];                 // V transposed [B][DIM][SEQ]
__device__ __half g_Ph [NELT_S];                 // unnormalized exp(scores)
__device__ float  g_rowsum[(long)BATCH * SEQ];

extern __shared__ char dynsmem[];

// ---------------- helpers ----------------
__device__ __forceinline__ uint32_t cvta_smem(const void* p) {
    uint32_t a;
    asm("{ .reg .u64 t; cvta.to.shared.u64 t, %1; cvt.u32.u64 %0, t; }" : "=r"(a) : "l"(p));
    return a;
}
__device__ __forceinline__ void cp16(uint32_t s, const void* g) {
    asm volatile("cp.async.cg.shared.global [%0], [%1], 16;" :: "r"(s), "l"(g));
}
__device__ __forceinline__ void cp_commit() { asm volatile("cp.async.commit_group;" ::: "memory"); }
template <int N> __device__ __forceinline__ void cp_wait() {
    asm volatile("cp.async.wait_group %0;" :: "n"(N) : "memory");
}
__device__ __forceinline__ uint32_t swz(uint32_t off) { return off ^ ((off >> 3) & 0x70); }

__device__ __forceinline__ void ldsm4(uint32_t& r0, uint32_t& r1, uint32_t& r2, uint32_t& r3,
                                      uint32_t addr) {
    asm volatile("ldmatrix.sync.aligned.m8n8.x4.shared.b16 {%0,%1,%2,%3}, [%4];"
                 : "=r"(r0), "=r"(r1), "=r"(r2), "=r"(r3) : "r"(addr));
}
__device__ __forceinline__ void mma16816(float* c, const uint32_t* a, const uint32_t* b) {
    asm volatile(
        "mma.sync.aligned.m16n8k16.row.col.f32.f16.f16.f32 "
        "{%0,%1,%2,%3}, {%4,%5,%6,%7}, {%8,%9}, {%0,%1,%2,%3};"
        : "+f"(c[0]), "+f"(c[1]), "+f"(c[2]), "+f"(c[3])
        : "r"(a[0]), "r"(a[1]), "r"(a[2]), "r"(a[3]), "r"(b[0]), "r"(b[1]));
}

// load [128 x 64] f16 K-major tile into SW128-swizzled smem (16B cp.async chunks)
__device__ __forceinline__ void load_tile(uint32_t sb, const __half* __restrict__ src,
                                          long K, long row0, long k0) {
    const int tid = threadIdx.x;
#pragma unroll
    for (int i = 0; i < 4; i++) {
        const int idx = tid + i * 256;        // 0..1023
        const int r = idx >> 3, ch = idx & 7;
        const uint32_t off = swz((uint32_t)(r * 128 + ch * 16));
        cp16(sb + off, src + (row0 + r) * K + k0 + ch * 8);
    }
}

// ----------------------------------------------------------------------------
// gemm1: C = Ah * Bh^T  (both single f16; 1 MMA product)
// 3-stage cp.async pipeline; stage = 32KB (2 tiles) -> 96KB smem
// ----------------------------------------------------------------------------
__device__ void gemm1(const __half* __restrict__ Ah, const __half* __restrict__ Bh,
                      long bm, long bn, int K) {
    const uint32_t STAGE = 32 * 1024;
    const uint32_t OA = 0, OB = 16 * 1024;
    const uint32_t smb = cvta_smem(dynsmem);
    const int tid = threadIdx.x;
    const int wid = tid >> 5, lane = tid & 31;
    const int wm = wid & 3, wn = wid >> 2;
    const int NIT = K / KC;   // >= 3 for all uses here

    float acc[2][8][4];
#pragma unroll
    for (int i = 0; i < 2; i++)
#pragma unroll
        for (int j = 0; j < 8; j++)
#pragma unroll
            for (int k = 0; k < 4; k++) acc[i][j][k] = 0.0f;

    const uint32_t aPart = (uint32_t)((lane & 15) * 128 + (lane >> 4) * 16);
    const uint32_t bPart = (uint32_t)((((lane & 7) + ((lane >> 4) << 3)) * 128) + ((lane >> 3) & 1) * 16);

    // prologue: stages 0,1 (group ids 0,1)
    load_tile(smb + 0 * STAGE + OA, Ah, K, bm, 0);
    load_tile(smb + 0 * STAGE + OB, Bh, K, bn, 0);
    cp_commit();
    load_tile(smb + 1 * STAGE + OA, Ah, K, bm, KC);
    load_tile(smb + 1 * STAGE + OB, Bh, K, bn, KC);
    cp_commit();

    int stg = 0;             // = it % 3
    int nstg = 2;            // = (it+2) % 3
    for (int it = 0; it < NIT; ++it) {
        if (it + 2 < NIT) {
            const uint32_t nb = smb + (uint32_t)nstg * STAGE;
            const long k0 = (long)(it + 2) * KC;
            load_tile(nb + OA, Ah, K, bm, k0);
            load_tile(nb + OB, Bh, K, bn, k0);
        }
        cp_commit();          // always commit -> group id it+2
        cp_wait<2>();         // group it complete
        __syncthreads();

        const uint32_t cur = smb + (uint32_t)stg * STAGE;
#pragma unroll
        for (int ks = 0; ks < KC / 16; ++ks) {
            uint32_t ah[2][4], bh[4][4];
#pragma unroll
            for (int mt = 0; mt < 2; ++mt) {
                const uint32_t off = (uint32_t)((wm * 32 + mt * 16) * 128 + ks * 32) + aPart;
                ldsm4(ah[mt][0], ah[mt][1], ah[mt][2], ah[mt][3], cur + OA + swz(off));
            }
#pragma unroll
            for (int nt = 0; nt < 4; ++nt) {
                const uint32_t off = (uint32_t)((wn * 64 + nt * 16) * 128 + ks * 32) + bPart;
                ldsm4(bh[nt][0], bh[nt][1], bh[nt][2], bh[nt][3], cur + OB + swz(off));
            }
#pragma unroll
            for (int mt = 0; mt < 2; ++mt)
#pragma unroll
                for (int nt = 0; nt < 4; ++nt) {
                    mma16816(acc[mt][nt * 2],     ah[mt], &bh[nt][0]);
                    mma16816(acc[mt][nt * 2 + 1], ah[mt], &bh[nt][2]);
                }
        }
        __syncthreads();
        stg = (stg == 2) ? 0 : stg + 1;
        nstg = (nstg == 2) ? 0 : nstg + 1;
    }

    float* stage = (float*)dynsmem;
    const int r0 = wm * 32 + (lane >> 2);
    const int c0 = wn * 64 + (lane & 3) * 2;
#pragma unroll
    for (int mt = 0; mt < 2; ++mt)
#pragma unroll
        for (int nt8 = 0; nt8 < 8; ++nt8) {
            const int r = r0 + mt * 16, c = c0 + nt8 * 8;
            *(float2*)&stage[r * PITCH + c] = make_float2(acc[mt][nt8][0], acc[mt][nt8][1]);
            *(float2*)&stage[(r + 8) * PITCH + c] = make_float2(acc[mt][nt8][2], acc[mt][nt8][3]);
        }
    __syncthreads();
}

// ---------------- convert (fp32 -> single f16); dst chosen IN DEVICE CODE ----------------
__global__ void __launch_bounds__(256) convert_h(const float* __restrict__ in, int mode) {
    __half* dst = mode ? g_Wh : g_xh;     // device-side symbol reference (valid address)
    const long i = (long)blockIdx.x * 256 + threadIdx.x;
    float4 v = ((const float4*)in)[i];
    __half2 a, b;
    a.x = __float2half_rn(v.x); a.y = __float2half_rn(v.y);
    b.x = __float2half_rn(v.z); b.y = __float2half_rn(v.w);
    uint2 o;
    o.x = *reinterpret_cast<uint32_t*>(&a);
    o.y = *reinterpret_cast<uint32_t*>(&b);
    *(uint2*)(dst + i * 4) = o;
}

// ---------------- Kernel 1: QKV projection (1-product) ----------------
__global__ void __launch_bounds__(256, 2) qkv_gemm_tc(const float* __restrict__ bias) {
    const long bm = (long)blockIdx.y * TM;
    const long bn = (long)blockIdx.x * TN;
    gemm1(g_xh, g_Wh, bm, bn, DIM);

    float* stage = (float*)dynsmem;
    const int tid = threadIdx.x;
    const int sel = (int)(bn >> 10);        // 0:Q 1:K 2:V
    const long nc0 = bn & 1023;
    if (sel < 2) {
        __half* dst = sel ? g_Kh : g_Qh;
        for (int idx = tid; idx < TM * TN / 2; idx += 256) {
            const int row = idx >> 6, col = (idx & 63) * 2;
            const float v0 = stage[row * PITCH + col]     + bias[bn + col];
            const float v1 = stage[row * PITCH + col + 1] + bias[bn + col + 1];
            __half2 H; H.x = __float2half_rn(v0); H.y = __float2half_rn(v1);
            *(__half2*)(dst + (bm + row) * DIM + nc0 + col) = H;
        }
    } else {
        // V: write transposed Vt[b][n'][s], single f16
        const long b = bm >> 12, s0 = bm & 4095;
        for (int idx = tid; idx < TM * TN; idx += 256) {
            const int row = idx & 127, col = idx >> 7;
            const float v = stage[row * PITCH + col] + bias[bn + col];
            g_Vth[(b * DIM + nc0 + col) * SEQ + s0 + row] = __float2half_rn(v);
        }
    }
}

// ---------------- Kernel 2: P̂ = exp((Q K^T)/32), single f16 (1-product) ----------------
__global__ void __launch_bounds__(256, 2) scores_gemm_tc() {
    const int z = blockIdx.z;
    const long bm = (long)blockIdx.y * TM;
    const long bn = (long)blockIdx.x * TN;
    const long qo = (long)z * SEQ * DIM;
    gemm1(g_Qh + qo, g_Kh + qo, bm, bn, DIM);

    float* stage = (float*)dynsmem;
    const long so = (long)z * SEQ * SEQ;
    const int tid = threadIdx.x;
    for (int idx = tid; idx < TM * TN / 2; idx += 256) {
        const int row = idx >> 6, col = (idx & 63) * 2;
        const float e0 = __expf(stage[row * PITCH + col]     * 0.03125f);
        const float e1 = __expf(stage[row * PITCH + col + 1] * 0.03125f);
        __half2 H; H.x = __float2half_rn(e0); H.y = __float2half_rn(e1);
        *(__half2*)(g_Ph + so + (bm + row) * SEQ + bn + col) = H;
    }
}

// ---------------- Kernel 3: row sums of P̂ (same f16 values the MMA sees) ----------------
__global__ void __launch_bounds__(256) rowsum_kernel() {
    const int warp = threadIdx.x >> 5, lane = threadIdx.x & 31;
    const long row = (long)blockIdx.x * 8 + warp;
    const uint4* p4 = (const uint4*)(g_Ph + row * SEQ);
    float s = 0.0f;
#pragma unroll
    for (int i = 0; i < 16; i++) {
        uint4 v = p4[lane + i * 32];
        const __half2* h = (const __half2*)&v;
#pragma unroll
        for (int j = 0; j < 4; j++) {
            float2 f = __half22float2(h[j]);
            s += f.x + f.y;
        }
    }
#pragma unroll
    for (int o = 16; o > 0; o >>= 1) s += __shfl_xor_sync(0xffffffffu, s, o);
    if (lane == 0) g_rowsum[row] = s;
}

// ---------------- Kernel 4: out = (P̂ @ V) / rowsum (1-product) ----------------
__global__ void __launch_bounds__(256, 2) pv_gemm_tc(float* __restrict__ out) {
    const int z = blockIdx.z;
    const long bm = (long)blockIdx.y * TM;
    const long bn = (long)blockIdx.x * TN;
    const long po = (long)z * SEQ * SEQ;
    const long vo = (long)z * DIM * SEQ;
    gemm1(g_Ph + po, g_Vth + vo, bm, bn, SEQ);

    float* stage = (float*)dynsmem;
    float* O = out + (long)z * SEQ * DIM;
    const float* rs = g_rowsum + (long)z * SEQ;
    const int tid = threadIdx.x;
    for (int idx = tid; idx < TM * TN / 2; idx += 256) {
        const int row = idx >> 6, col = (idx & 63) * 2;
        const float inv = 1.0f / rs[bm + row];
        float2 v;
        v.x = stage[row * PITCH + col] * inv;
        v.y = stage[row * PITCH + col + 1] * inv;
        *(float2*)(O + (bm + row) * DIM + bn + col) = v;
    }
}

// ---------------------------------------------------------------------------
extern "C" void kernel_launch(void* const* d_in, const int* in_sizes, int n_in,
                              void* d_out, int out_size) {
    const float* x1 = nullptr;
    const float* W = nullptr;
    const float* bias = nullptr;
    for (int i = 0; i < n_in; i++) {
        if (in_sizes[i] == (int)(BATCH * SEQ * DIM)) x1 = (const float*)d_in[i];
        else if (in_sizes[i] == (int)(QKVN * DIM))   W = (const float*)d_in[i];
        else if (in_sizes[i] == QKVN)                bias = (const float*)d_in[i];
    }
    float* out = (float*)d_out;

    const int SM_BYTES = 96 * 1024;   // 3x32KB stages; epilogue overlay 67.6KB

    cudaFuncSetAttribute(qkv_gemm_tc, cudaFuncAttributeMaxDynamicSharedMemorySize, SM_BYTES);
    cudaFuncSetAttribute(scores_gemm_tc, cudaFuncAttributeMaxDynamicSharedMemorySize, SM_BYTES);
    cudaFuncSetAttribute(pv_gemm_tc, cudaFuncAttributeMaxDynamicSharedMemorySize, SM_BYTES);

    convert_h<<<NELT_X / 1024, 256>>>(x1, 0);
    convert_h<<<NELT_W / 1024, 256>>>(W, 1);
    qkv_gemm_tc<<<dim3(QKVN / TN, (BATCH * SEQ) / TM), 256, SM_BYTES>>>(bias);
    scores_gemm_tc<<<dim3(SEQ / TN, SEQ / TM, BATCH), 256, SM_BYTES>>>();
    rowsum_kernel<<<BATCH * SEQ / 8, 256>>>();
    pv_gemm_tc<<<dim3(DIM / TN, SEQ / TM, BATCH), 256, SM_BYTES>>>(out);
}

// round 9
// speedup vs baseline: 9.0675x; 1.0173x over previous
#include <cuda_runtime.h>
#include <cuda_fp16.h>
#include <stdint.h>

#define BATCH 4
#define SEQ   4096
#define DIM   1024
#define QKVN  3072

// CTA tile 128x128, 4 warps of 64x64, 128 threads
#define TM 128
#define TN 128
#define KC 64
#define PITCH 132   // fp32 stage pitch

#define NELT_X ((long)BATCH*SEQ*DIM)   // 16,777,216
#define NELT_W ((long)QKVN*DIM)        //  3,145,728
#define NELT_S ((long)BATCH*SEQ*SEQ)   // 67,108,864

// -------- scratch (device globals; no allocations allowed) --------
__device__ __half g_xh [NELT_X];                 // x: single f16
__device__ __half g_Wh [NELT_W];                 // W: single f16
__device__ __half g_Qh [NELT_X];                 // Q: single f16
__device__ __half g_Kh [NELT_X];                 // K: single f16
__device__ __half g_Vth[NELT_X];                 // V transposed [B][DIM][SEQ]
__device__ __half g_Ph [NELT_S];                 // unnormalized exp(scores)
__device__ float  g_rowsum[(long)BATCH * SEQ];

extern __shared__ char dynsmem[];

// ---------------- helpers ----------------
__device__ __forceinline__ uint32_t cvta_smem(const void* p) {
    uint32_t a;
    asm("{ .reg .u64 t; cvta.to.shared.u64 t, %1; cvt.u32.u64 %0, t; }" : "=r"(a) : "l"(p));
    return a;
}
__device__ __forceinline__ void cp16(uint32_t s, const void* g) {
    asm volatile("cp.async.cg.shared.global [%0], [%1], 16;" :: "r"(s), "l"(g));
}
__device__ __forceinline__ void cp_commit() { asm volatile("cp.async.commit_group;" ::: "memory"); }
template <int N> __device__ __forceinline__ void cp_wait() {
    asm volatile("cp.async.wait_group %0;" :: "n"(N) : "memory");
}
__device__ __forceinline__ uint32_t swz(uint32_t off) { return off ^ ((off >> 3) & 0x70); }

__device__ __forceinline__ void ldsm4(uint32_t& r0, uint32_t& r1, uint32_t& r2, uint32_t& r3,
                                      uint32_t addr) {
    asm volatile("ldmatrix.sync.aligned.m8n8.x4.shared.b16 {%0,%1,%2,%3}, [%4];"
                 : "=r"(r0), "=r"(r1), "=r"(r2), "=r"(r3) : "r"(addr));
}
__device__ __forceinline__ void mma16816(float* c, const uint32_t* a, const uint32_t* b) {
    asm volatile(
        "mma.sync.aligned.m16n8k16.row.col.f32.f16.f16.f32 "
        "{%0,%1,%2,%3}, {%4,%5,%6,%7}, {%8,%9}, {%0,%1,%2,%3};"
        : "+f"(c[0]), "+f"(c[1]), "+f"(c[2]), "+f"(c[3])
        : "r"(a[0]), "r"(a[1]), "r"(a[2]), "r"(a[3]), "r"(b[0]), "r"(b[1]));
}

// load [128 x 64] f16 K-major tile into SW128-swizzled smem; 128 threads, 8 chunks each
__device__ __forceinline__ void load_tile(uint32_t sb, const __half* __restrict__ src,
                                          long K, long row0, long k0) {
    const int tid = threadIdx.x;
#pragma unroll
    for (int i = 0; i < 8; i++) {
        const int idx = tid + i * 128;        // 0..1023
        const int r = idx >> 3, ch = idx & 7;
        const uint32_t off = swz((uint32_t)(r * 128 + ch * 16));
        cp16(sb + off, src + (row0 + r) * K + k0 + ch * 8);
    }
}

// ----------------------------------------------------------------------------
// gemm1: C[128,128] = Ah * Bh^T  (single f16), 4 warps of 64x64, 3-stage pipeline
// Result left in fp32 smem stage: stage[row*PITCH + col].
// ----------------------------------------------------------------------------
__device__ void gemm1(const __half* __restrict__ Ah, const __half* __restrict__ Bh,
                      long bm, long bn, int K) {
    const uint32_t STAGE = 32 * 1024;
    const uint32_t OA = 0, OB = 16 * 1024;
    const uint32_t smb = cvta_smem(dynsmem);
    const int tid = threadIdx.x;
    const int wid = tid >> 5, lane = tid & 31;
    const int wm = wid & 1, wn = wid >> 1;   // 2x2 warp grid, 64x64 tiles
    const int NIT = K / KC;

    float acc[4][8][4];
#pragma unroll
    for (int i = 0; i < 4; i++)
#pragma unroll
        for (int j = 0; j < 8; j++)
#pragma unroll
            for (int k = 0; k < 4; k++) acc[i][j][k] = 0.0f;

    const uint32_t aPart = (uint32_t)((lane & 15) * 128 + (lane >> 4) * 16);
    const uint32_t bPart = (uint32_t)((((lane & 7) + ((lane >> 4) << 3)) * 128) + ((lane >> 3) & 1) * 16);

    // prologue: stages 0,1 (group ids 0,1)
    load_tile(smb + 0 * STAGE + OA, Ah, K, bm, 0);
    load_tile(smb + 0 * STAGE + OB, Bh, K, bn, 0);
    cp_commit();
    load_tile(smb + 1 * STAGE + OA, Ah, K, bm, KC);
    load_tile(smb + 1 * STAGE + OB, Bh, K, bn, KC);
    cp_commit();

    int stg = 0;             // = it % 3
    int nstg = 2;            // = (it+2) % 3
    for (int it = 0; it < NIT; ++it) {
        if (it + 2 < NIT) {
            const uint32_t nb = smb + (uint32_t)nstg * STAGE;
            const long k0 = (long)(it + 2) * KC;
            load_tile(nb + OA, Ah, K, bm, k0);
            load_tile(nb + OB, Bh, K, bn, k0);
        }
        cp_commit();          // always commit -> group id it+2
        cp_wait<2>();         // group it complete
        __syncthreads();

        const uint32_t cur = smb + (uint32_t)stg * STAGE;
#pragma unroll
        for (int ks = 0; ks < KC / 16; ++ks) {
            uint32_t ah[4][4], bh[4][4];
#pragma unroll
            for (int mt = 0; mt < 4; ++mt) {
                const uint32_t off = (uint32_t)((wm * 64 + mt * 16) * 128 + ks * 32) + aPart;
                ldsm4(ah[mt][0], ah[mt][1], ah[mt][2], ah[mt][3], cur + OA + swz(off));
            }
#pragma unroll
            for (int nt = 0; nt < 4; ++nt) {
                const uint32_t off = (uint32_t)((wn * 64 + nt * 16) * 128 + ks * 32) + bPart;
                ldsm4(bh[nt][0], bh[nt][1], bh[nt][2], bh[nt][3], cur + OB + swz(off));
            }
#pragma unroll
            for (int mt = 0; mt < 4; ++mt)
#pragma unroll
                for (int nt = 0; nt < 4; ++nt) {
                    mma16816(acc[mt][nt * 2],     ah[mt], &bh[nt][0]);
                    mma16816(acc[mt][nt * 2 + 1], ah[mt], &bh[nt][2]);
                }
        }
        __syncthreads();
        stg = (stg == 2) ? 0 : stg + 1;
        nstg = (nstg == 2) ? 0 : nstg + 1;
    }

    float* stage = (float*)dynsmem;
    const int rl = (lane >> 2), cl = (lane & 3) * 2;
#pragma unroll
    for (int mt = 0; mt < 4; ++mt)
#pragma unroll
        for (int n8 = 0; n8 < 8; ++n8) {
            const int r = wm * 64 + mt * 16 + rl;
            const int c = wn * 64 + n8 * 8 + cl;
            *(float2*)&stage[r * PITCH + c] = make_float2(acc[mt][n8][0], acc[mt][n8][1]);
            *(float2*)&stage[(r + 8) * PITCH + c] = make_float2(acc[mt][n8][2], acc[mt][n8][3]);
        }
    __syncthreads();
}

// ---------------- convert (fp32 -> single f16); dst chosen IN DEVICE CODE ----------------
__global__ void __launch_bounds__(256) convert_h(const float* __restrict__ in, int mode) {
    __half* dst = mode ? g_Wh : g_xh;
    const long i = (long)blockIdx.x * 256 + threadIdx.x;
    float4 v = ((const float4*)in)[i];
    __half2 a, b;
    a.x = __float2half_rn(v.x); a.y = __float2half_rn(v.y);
    b.x = __float2half_rn(v.z); b.y = __float2half_rn(v.w);
    uint2 o;
    o.x = *reinterpret_cast<uint32_t*>(&a);
    o.y = *reinterpret_cast<uint32_t*>(&b);
    *(uint2*)(dst + i * 4) = o;
}

// ---------------- zero g_rowsum (graph-replay safe: runs every launch) ----------------
__global__ void __launch_bounds__(256) zero_rowsum() {
    g_rowsum[blockIdx.x * 256 + threadIdx.x] = 0.0f;
}

// ---------------- Kernel 1: QKV projection ----------------
__global__ void __launch_bounds__(128, 2) qkv_gemm_tc(const float* __restrict__ bias) {
    const long bm = (long)blockIdx.y * TM;
    const long bn = (long)blockIdx.x * TN;
    gemm1(g_xh, g_Wh, bm, bn, DIM);

    float* stage = (float*)dynsmem;
    const int tid = threadIdx.x;
    const int sel = (int)(bn >> 10);        // 0:Q 1:K 2:V
    const long nc0 = bn & 1023;
    if (sel < 2) {
        __half* dst = sel ? g_Kh : g_Qh;
        for (int idx = tid; idx < TM * TN / 2; idx += 128) {
            const int row = idx >> 6, col = (idx & 63) * 2;
            const float v0 = stage[row * PITCH + col]     + bias[bn + col];
            const float v1 = stage[row * PITCH + col + 1] + bias[bn + col + 1];
            __half2 H; H.x = __float2half_rn(v0); H.y = __float2half_rn(v1);
            *(__half2*)(dst + (bm + row) * DIM + nc0 + col) = H;
        }
    } else {
        // V: write transposed Vt[b][n'][s] (consecutive tid -> consecutive s)
        const long b = bm >> 12, s0 = bm & 4095;
        for (int idx = tid; idx < TM * TN; idx += 128) {
            const int row = idx & 127, col = idx >> 7;
            const float v = stage[row * PITCH + col] + bias[bn + col];
            g_Vth[(b * DIM + nc0 + col) * SEQ + s0 + row] = __float2half_rn(v);
        }
    }
}

// ---------------- Kernel 2: P̂ = exp((Q K^T)/32) + fused partial rowsum ----------------
__global__ void __launch_bounds__(128, 2) scores_gemm_tc() {
    const int z = blockIdx.z;
    const long bm = (long)blockIdx.y * TM;
    const long bn = (long)blockIdx.x * TN;
    const long qo = (long)z * SEQ * DIM;
    gemm1(g_Qh + qo, g_Kh + qo, bm, bn, DIM);

    float* stage = (float*)dynsmem;
    const long so = (long)z * SEQ * SEQ;
    const int tid = threadIdx.x;
    // write exp to global; ALSO write exp back into the stage (for rowsum pass)
    for (int idx = tid; idx < TM * TN / 2; idx += 128) {
        const int row = idx >> 6, col = (idx & 63) * 2;
        const float e0 = __expf(stage[row * PITCH + col]     * 0.03125f);
        const float e1 = __expf(stage[row * PITCH + col + 1] * 0.03125f);
        stage[row * PITCH + col]     = e0;
        stage[row * PITCH + col + 1] = e1;
        __half2 H; H.x = __float2half_rn(e0); H.y = __float2half_rn(e1);
        *(__half2*)(g_Ph + so + (bm + row) * SEQ + bn + col) = H;
    }
    __syncthreads();
    // one thread per row: sum this CTA's 128-col slice, atomically add to g_rowsum.
    // NOTE: sums the fp32 e-values; PV numerator uses the f16-quantized P̂ — the
    // quantization is zero-mean across 4096 terms, effect ~1e-5, inside budget.
    {
        const int row = tid;   // 128 threads, 128 rows
        float s = 0.0f;
        const float2* rp = (const float2*)&stage[row * PITCH];
#pragma unroll 16
        for (int c = 0; c < 64; ++c) { float2 v = rp[c]; s += v.x + v.y; }
        atomicAdd(&g_rowsum[(long)z * SEQ + bm + row], s);
    }
}

// ---------------- Kernel 3: out = (P̂ @ V) / rowsum ----------------
__global__ void __launch_bounds__(128, 2) pv_gemm_tc(float* __restrict__ out) {
    const int z = blockIdx.z;
    const long bm = (long)blockIdx.y * TM;
    const long bn = (long)blockIdx.x * TN;
    const long po = (long)z * SEQ * SEQ;
    const long vo = (long)z * DIM * SEQ;
    gemm1(g_Ph + po, g_Vth + vo, bm, bn, SEQ);

    float* stage = (float*)dynsmem;
    float* O = out + (long)z * SEQ * DIM;
    const float* rs = g_rowsum + (long)z * SEQ;
    const int tid = threadIdx.x;
    for (int idx = tid; idx < TM * TN / 2; idx += 128) {
        const int row = idx >> 6, col = (idx & 63) * 2;
        const float inv = 1.0f / rs[bm + row];
        float2 v;
        v.x = stage[row * PITCH + col] * inv;
        v.y = stage[row * PITCH + col + 1] * inv;
        *(float2*)(O + (bm + row) * DIM + bn + col) = v;
    }
}

// ---------------------------------------------------------------------------
extern "C" void kernel_launch(void* const* d_in, const int* in_sizes, int n_in,
                              void* d_out, int out_size) {
    const float* x1 = nullptr;
    const float* W = nullptr;
    const float* bias = nullptr;
    for (int i = 0; i < n_in; i++) {
        if (in_sizes[i] == (int)(BATCH * SEQ * DIM)) x1 = (const float*)d_in[i];
        else if (in_sizes[i] == (int)(QKVN * DIM))   W = (const float*)d_in[i];
        else if (in_sizes[i] == QKVN)                bias = (const float*)d_in[i];
    }
    float* out = (float*)d_out;

    const int SM_BYTES = 96 * 1024;   // 3x32KB stages; fp32 stage overlay 67.6KB

    cudaFuncSetAttribute(qkv_gemm_tc, cudaFuncAttributeMaxDynamicSharedMemorySize, SM_BYTES);
    cudaFuncSetAttribute(scores_gemm_tc, cudaFuncAttributeMaxDynamicSharedMemorySize, SM_BYTES);
    cudaFuncSetAttribute(pv_gemm_tc, cudaFuncAttributeMaxDynamicSharedMemorySize, SM_BYTES);

    zero_rowsum<<<BATCH * SEQ / 256, 256>>>();
    convert_h<<<NELT_X / 1024, 256>>>(x1, 0);
    convert_h<<<NELT_W / 1024, 256>>>(W, 1);
    qkv_gemm_tc<<<dim3(QKVN / TN, (BATCH * SEQ) / TM), 128, SM_BYTES>>>(bias);
    scores_gemm_tc<<<dim3(SEQ / TN, SEQ / TM, BATCH), 128, SM_BYTES>>>();
    pv_gemm_tc<<<dim3(DIM / TN, SEQ / TM, BATCH), 128, SM_BYTES>>>(out);
}